// round 5
// baseline (speedup 1.0000x reference)
#include <cuda_runtime.h>

#define KNN_K 16
#define NB    128      // z bins per batch
#define TQ    128      // threads per query block
#define MAXN  8
#define MAXP  8192

// Static scratch (allocations are forbidden).
__device__ float4 g_pack[MAXN * MAXP];      // bin-sorted targets (x,y,z,||p||^2)
__device__ int    g_tidx[MAXN * MAXP];      // original target index
__device__ int    g_qidx[MAXN * MAXP];      // bin-sorted query original index
__device__ int    g_bstart[MAXN * (NB + 1)];
__device__ int    g_cnt[MAXN * NB];         // scatter cursors (targets)
__device__ int    g_qcnt[MAXN * NB];        // scatter cursors (queries)
__device__ float  g_zmin[MAXN], g_inv[MAXN], g_w[MAXN];

// ||p||^2 with reference rounding: rn(rn(x*x + y*y) + z*z), products rounded.
__device__ __forceinline__ float sumsq_ref(float x, float y, float z) {
    return __fadd_rn(__fadd_rn(__fmul_rn(x, x), __fmul_rn(y, y)),
                     __fmul_rn(z, z));
}

__device__ __forceinline__ int zbin(float z, float zmin, float inv) {
    int b = (int)((z - zmin) * inv);
    return min(NB - 1, max(0, b));
}

// One block per batch: z min/max over valid targets, histograms for targets
// and queries, exclusive scans -> bin starts + scatter cursors.
__global__ void setup_kernel(const float* __restrict__ p1,
                             const float* __restrict__ p2,
                             const int* __restrict__ len1,
                             const int* __restrict__ len2,
                             int P1, int P2) {
    int n = blockIdx.x, tid = threadIdx.x;
    int L1 = len1[n], L2 = len2[n];
    __shared__ float sred[256];
    __shared__ int hist[NB], qh[NB];

    float mn = 1e30f, mx = -1e30f;
    for (int j = tid; j < L2; j += 256) {
        float z = p2[((size_t)n * P2 + j) * 3 + 2];
        mn = fminf(mn, z); mx = fmaxf(mx, z);
    }
    sred[tid] = mn; __syncthreads();
    for (int s = 128; s > 0; s >>= 1) {
        if (tid < s) sred[tid] = fminf(sred[tid], sred[tid + s]);
        __syncthreads();
    }
    float zmin = sred[0]; __syncthreads();
    sred[tid] = mx; __syncthreads();
    for (int s = 128; s > 0; s >>= 1) {
        if (tid < s) sred[tid] = fmaxf(sred[tid], sred[tid + s]);
        __syncthreads();
    }
    float zmax = sred[0]; __syncthreads();

    float range = fmaxf(zmax - zmin, 1e-20f);
    float w = range / NB;
    float inv = (float)NB / range;
    if (tid == 0) { g_zmin[n] = zmin; g_inv[n] = inv; g_w[n] = w; }

    for (int b = tid; b < NB; b += 256) { hist[b] = 0; qh[b] = 0; }
    __syncthreads();
    for (int j = tid; j < L2; j += 256) {
        float z = p2[((size_t)n * P2 + j) * 3 + 2];
        atomicAdd(&hist[zbin(z, zmin, inv)], 1);
    }
    for (int j = tid; j < L1; j += 256) {
        float z = p1[((size_t)n * P1 + j) * 3 + 2];
        atomicAdd(&qh[zbin(z, zmin, inv)], 1);
    }
    __syncthreads();
    if (tid == 0) {
        int acc = 0;
        for (int b = 0; b < NB; b++) {
            g_bstart[n * (NB + 1) + b] = acc;
            g_cnt[n * NB + b] = acc;
            acc += hist[b];
        }
        g_bstart[n * (NB + 1) + NB] = acc;
        int qa = 0;
        for (int b = 0; b < NB; b++) { g_qcnt[n * NB + b] = qa; qa += qh[b]; }
    }
}

__global__ void scatter_kernel(const float* __restrict__ p1,
                               const float* __restrict__ p2,
                               const int* __restrict__ len1,
                               const int* __restrict__ len2,
                               int Nn, int P1, int P2) {
    int t = blockIdx.x * blockDim.x + threadIdx.x;
    int P = max(P1, P2);
    if (t >= Nn * P) return;
    int n = t / P;
    int j = t - n * P;
    float zmin = g_zmin[n], inv = g_inv[n];
    if (j < P2 && j < len2[n]) {
        const float* p = p2 + ((size_t)n * P2 + j) * 3;
        float x = p[0], y = p[1], z = p[2];
        int b = zbin(z, zmin, inv);
        int pos = atomicAdd(&g_cnt[n * NB + b], 1);
        g_pack[n * MAXP + pos] = make_float4(x, y, z, sumsq_ref(x, y, z));
        g_tidx[n * MAXP + pos] = j;
    }
    if (j < P1 && j < len1[n]) {
        float z = p1[((size_t)n * P1 + j) * 3 + 2];
        int b = zbin(z, zmin, inv);
        int pos = atomicAdd(&g_qcnt[n * NB + b], 1);
        g_qidx[n * MAXP + pos] = j;
    }
}

__global__ void zero_kernel(float* __restrict__ out, long long total) {
    long long t = (long long)blockIdx.x * blockDim.x + threadIdx.x;
    long long stride = (long long)gridDim.x * blockDim.x;
    for (; t < total; t += stride) out[t] = 0.0f;
}

// Selection is a total order on (distance, original index): result is
// independent of candidate scan order, matching lax.top_k (lowest index
// first among exact ties).
#define PROCESS_BIN(b)                                                          \
    {                                                                           \
        int t0 = bs[b], t1 = bs[(b) + 1];                                       \
        _Pragma("unroll 2")                                                     \
        for (int t = t0; t < t1; ++t) {                                         \
            float4 q = __ldg(&pk[t]);                                           \
            float dot = __fmaf_rn(z1, q.z,                                      \
                        __fmaf_rn(y1, q.y,                                      \
                        __fmul_rn(x1, q.x)));                                   \
            float d = __fmaf_rn(-2.0f, dot, __fadd_rn(s1, q.w));                \
            int jj = __ldg(&tix[t]);                                            \
            if (d < best[KNN_K - 1] ||                                          \
                (d == best[KNN_K - 1] && jj < bi[KNN_K - 1])) {                 \
                best[KNN_K - 1] = d;                                            \
                bi[KNN_K - 1] = jj;                                             \
                _Pragma("unroll")                                               \
                for (int k = KNN_K - 1; k > 0; --k) {                           \
                    if (best[k] < best[k - 1] ||                                \
                        (best[k] == best[k - 1] && bi[k] < bi[k - 1])) {        \
                        float tf = best[k - 1]; best[k - 1] = best[k];          \
                        best[k] = tf;                                           \
                        int ti = bi[k - 1]; bi[k - 1] = bi[k]; bi[k] = ti;      \
                    } else break;                                               \
                }                                                               \
            }                                                                   \
        }                                                                       \
    }

__global__ __launch_bounds__(TQ) void knn_kernel(
    const float* __restrict__ p1,
    const int* __restrict__ len1,
    float* __restrict__ out,
    int Nn, int P1, int P2, long long NPK) {

    int nbq = (P1 + TQ - 1) / TQ;
    int n = blockIdx.x / nbq;
    int qs = (blockIdx.x - n * nbq) * TQ + threadIdx.x;   // sorted query slot
    int L1 = len1[n];
    if (qs >= L1) return;                                  // zeros pre-written

    int i = g_qidx[n * MAXP + qs];                         // original query idx
    const float* p = p1 + ((size_t)n * P1 + i) * 3;
    float x1 = p[0], y1 = p[1], z1 = p[2];
    float s1 = sumsq_ref(x1, y1, z1);

    float zmin = g_zmin[n], inv = g_inv[n], w = g_w[n];
    const float4* pk = g_pack + (size_t)n * MAXP;
    const int* tix = g_tidx + (size_t)n * MAXP;
    const int* bs = g_bstart + n * (NB + 1);

    float best[KNN_K];
    int bi[KNN_K];
#pragma unroll
    for (int k = 0; k < KNN_K; k++) {
        best[k] = __int_as_float(0x7f800000);
        bi[k] = 0x7fffffff;   // sentinel: any real candidate wins ties
    }

    int c = zbin(z1, zmin, inv);
    PROCESS_BIN(c);

    const float eps = 1e-4f;
    int r = c + 1, l = c - 1;
    bool ro = true, lo = true;
    while (ro || lo) {
        if (ro) {
            bool stop = (r >= NB);
            if (!stop) {
                float dz = fmaxf(zmin + (float)r * w - z1, 0.0f);
                stop = (dz * dz > best[KNN_K - 1] + eps);
            }
            if (stop) ro = false;
            else { PROCESS_BIN(r); ++r; }
        }
        if (lo) {
            bool stop = (l < 0);
            if (!stop) {
                float dz = fmaxf(z1 - (zmin + (float)(l + 1) * w), 0.0f);
                stop = (dz * dz > best[KNN_K - 1] + eps);
            }
            if (stop) lo = false;
            else { PROCESS_BIN(l); --l; }
        }
    }

    long long o = ((long long)n * P1 + i) * KNN_K;
#pragma unroll
    for (int k = 0; k < KNN_K; k++) {
        out[o + k] = (float)bi[k];
        out[NPK + o + k] = best[k];
    }
}

extern "C" void kernel_launch(void* const* d_in, const int* in_sizes, int n_in,
                              void* d_out, int out_size) {
    // Classify inputs by size: tiny -> lengths, large -> points (order preserved).
    const float* pts[2] = {0, 0};
    const int* lens[2] = {0, 0};
    int lsz[2] = {0, 0};
    int psz[2] = {0, 0};
    int npts = 0, nlen = 0;
    for (int i = 0; i < n_in; i++) {
        if (in_sizes[i] <= 1024) {
            if (nlen < 2) { lens[nlen] = (const int*)d_in[i]; lsz[nlen] = in_sizes[i]; nlen++; }
        } else {
            if (npts < 2) { pts[npts] = (const float*)d_in[i]; psz[npts] = in_sizes[i]; npts++; }
        }
    }
    const float* p1 = pts[0];
    const float* p2 = pts[1];
    const int* l1 = lens[0];
    const int* l2 = lens[1];

    int Nn = lsz[0];
    int P1 = psz[0] / (3 * Nn);
    int P2 = psz[1] / (3 * Nn);
    long long NPK = (long long)out_size / 2;   // first half idx, second half dists

    setup_kernel<<<Nn, 256>>>(p1, p2, l1, l2, P1, P2);

    int P = (P1 > P2) ? P1 : P2;
    scatter_kernel<<<(Nn * P + 255) / 256, 256>>>(p1, p2, l1, l2, Nn, P1, P2);

    zero_kernel<<<512, 256>>>((float*)d_out, (long long)out_size);

    int nbq = (P1 + TQ - 1) / TQ;
    knn_kernel<<<Nn * nbq, TQ>>>(p1, l1, (float*)d_out, Nn, P1, P2, NPK);
}

// round 6
// speedup vs baseline: 3.4250x; 3.4250x over previous
#include <cuda_runtime.h>

#define KNN_K 16
#define NB    128      // z bins per batch
#define TQ    128      // threads per query block
#define CH    1024     // SMEM chunk (candidates)
#define C0    768      // initial window target count
#define MAXN  8
#define MAXP  8192

// Static scratch (allocations are forbidden).
__device__ float4 g_pack[MAXN * MAXP];      // bin-sorted targets (x,y,z,||p||^2)
__device__ int    g_tidx[MAXN * MAXP];      // original target index
__device__ int    g_qidx[MAXN * MAXP];      // bin-sorted query original index
__device__ int    g_bstart[MAXN * (NB + 1)];
__device__ int    g_cnt[MAXN * NB];         // scatter cursors (targets)
__device__ int    g_qcnt[MAXN * NB];        // scatter cursors (queries)
__device__ float  g_zmin[MAXN], g_inv[MAXN], g_w[MAXN];

// ||p||^2 with reference rounding: rn(rn(x*x + y*y) + z*z), products rounded.
__device__ __forceinline__ float sumsq_ref(float x, float y, float z) {
    return __fadd_rn(__fadd_rn(__fmul_rn(x, x), __fmul_rn(y, y)),
                     __fmul_rn(z, z));
}

__device__ __forceinline__ int zbin(float z, float zmin, float inv) {
    int b = (int)((z - zmin) * inv);
    return min(NB - 1, max(0, b));
}

__global__ void setup_kernel(const float* __restrict__ p1,
                             const float* __restrict__ p2,
                             const int* __restrict__ len1,
                             const int* __restrict__ len2,
                             int P1, int P2) {
    int n = blockIdx.x, tid = threadIdx.x;
    int L1 = len1[n], L2 = len2[n];
    __shared__ float sred[256];
    __shared__ int hist[NB], qh[NB];

    float mn = 1e30f, mx = -1e30f;
    for (int j = tid; j < L2; j += 256) {
        float z = p2[((size_t)n * P2 + j) * 3 + 2];
        mn = fminf(mn, z); mx = fmaxf(mx, z);
    }
    sred[tid] = mn; __syncthreads();
    for (int s = 128; s > 0; s >>= 1) {
        if (tid < s) sred[tid] = fminf(sred[tid], sred[tid + s]);
        __syncthreads();
    }
    float zmin = sred[0]; __syncthreads();
    sred[tid] = mx; __syncthreads();
    for (int s = 128; s > 0; s >>= 1) {
        if (tid < s) sred[tid] = fmaxf(sred[tid], sred[tid + s]);
        __syncthreads();
    }
    float zmax = sred[0]; __syncthreads();

    float range = fmaxf(zmax - zmin, 1e-20f);
    float w = range / NB;
    float inv = (float)NB / range;
    if (tid == 0) { g_zmin[n] = zmin; g_inv[n] = inv; g_w[n] = w; }

    for (int b = tid; b < NB; b += 256) { hist[b] = 0; qh[b] = 0; }
    __syncthreads();
    for (int j = tid; j < L2; j += 256) {
        float z = p2[((size_t)n * P2 + j) * 3 + 2];
        atomicAdd(&hist[zbin(z, zmin, inv)], 1);
    }
    for (int j = tid; j < L1; j += 256) {
        float z = p1[((size_t)n * P1 + j) * 3 + 2];
        atomicAdd(&qh[zbin(z, zmin, inv)], 1);
    }
    __syncthreads();
    if (tid == 0) {
        int acc = 0;
        for (int b = 0; b < NB; b++) {
            g_bstart[n * (NB + 1) + b] = acc;
            g_cnt[n * NB + b] = acc;
            acc += hist[b];
        }
        g_bstart[n * (NB + 1) + NB] = acc;
        int qa = 0;
        for (int b = 0; b < NB; b++) { g_qcnt[n * NB + b] = qa; qa += qh[b]; }
    }
}

__global__ void scatter_kernel(const float* __restrict__ p1,
                               const float* __restrict__ p2,
                               const int* __restrict__ len1,
                               const int* __restrict__ len2,
                               int Nn, int P1, int P2) {
    int t = blockIdx.x * blockDim.x + threadIdx.x;
    int P = max(P1, P2);
    if (t >= Nn * P) return;
    int n = t / P;
    int j = t - n * P;
    float zmin = g_zmin[n], inv = g_inv[n];
    if (j < P2 && j < len2[n]) {
        const float* p = p2 + ((size_t)n * P2 + j) * 3;
        float x = p[0], y = p[1], z = p[2];
        int b = zbin(z, zmin, inv);
        int pos = atomicAdd(&g_cnt[n * NB + b], 1);
        g_pack[n * MAXP + pos] = make_float4(x, y, z, sumsq_ref(x, y, z));
        g_tidx[n * MAXP + pos] = j;
    }
    if (j < P1 && j < len1[n]) {
        float z = p1[((size_t)n * P1 + j) * 3 + 2];
        int b = zbin(z, zmin, inv);
        int pos = atomicAdd(&g_qcnt[n * NB + b], 1);
        g_qidx[n * MAXP + pos] = j;
    }
}

__global__ void zero_kernel(float* __restrict__ out, long long total) {
    long long t = (long long)blockIdx.x * blockDim.x + threadIdx.x;
    long long stride = (long long)gridDim.x * blockDim.x;
    for (; t < total; t += stride) out[t] = 0.0f;
}

#define LEX_LT(da, ia, db, ib) (((da) < (db)) || (((da) == (db)) && ((ia) < (ib))))

// Predicated (branchless) compare-exchange of slots k and k-1.
#define STAGE(k)                                                               \
    {                                                                          \
        bool c = LEX_LT(best[k], bi[k], best[k - 1], bi[k - 1]);               \
        float tf = best[k - 1]; int ti = bi[k - 1];                            \
        best[k - 1] = c ? best[k] : best[k - 1];                               \
        bi[k - 1]   = c ? bi[k]   : bi[k - 1];                                 \
        best[k] = c ? tf : best[k];                                            \
        bi[k]   = c ? ti : bi[k];                                              \
    }

// Stream candidates [gstart, gend) through SMEM; total-order selection on
// (d, idx) -> result independent of scan order (matches lax.top_k ties).
#define SCAN_RANGE(gstart, gend)                                               \
    for (int base = (gstart); base < (gend); base += CH) {                     \
        int m = min(CH, (gend) - base);                                        \
        for (int t = threadIdx.x; t < m; t += TQ) {                            \
            sh4[t] = __ldg(&pk[base + t]);                                     \
            shi[t] = __ldg(&tix[base + t]);                                    \
        }                                                                      \
        __syncthreads();                                                       \
        _Pragma("unroll 2")                                                    \
        for (int t = 0; t < m; ++t) {                                          \
            float4 q = sh4[t];                                                 \
            float dot = __fmaf_rn(z1, q.z,                                     \
                        __fmaf_rn(y1, q.y,                                     \
                        __fmul_rn(x1, q.x)));                                  \
            float d = __fmaf_rn(-2.0f, dot, __fadd_rn(s1, q.w));               \
            if (d <= best[KNN_K - 1]) {                                        \
                int jj = shi[t];                                               \
                if (LEX_LT(d, jj, best[KNN_K - 1], bi[KNN_K - 1])) {           \
                    best[KNN_K - 1] = d; bi[KNN_K - 1] = jj;                   \
                    STAGE(15); STAGE(14); STAGE(13);                           \
                    if (LEX_LT(best[12], bi[12], best[11], bi[11])) {          \
                        _Pragma("unroll")                                      \
                        for (int k = 12; k > 0; --k) {                         \
                            bool c = LEX_LT(best[k], bi[k],                    \
                                            best[k - 1], bi[k - 1]);           \
                            if (!c) break;                                     \
                            float tf = best[k - 1]; int ti = bi[k - 1];        \
                            best[k - 1] = best[k]; bi[k - 1] = bi[k];          \
                            best[k] = tf; bi[k] = ti;                          \
                        }                                                      \
                    }                                                          \
                }                                                              \
            }                                                                  \
        }                                                                      \
        __syncthreads();                                                       \
    }

__global__ __launch_bounds__(TQ) void knn_kernel(
    const float* __restrict__ p1,
    const int* __restrict__ len1,
    float* __restrict__ out,
    int Nn, int P1, int P2, long long NPK) {

    __shared__ float4 sh4[CH];
    __shared__ int shi[CH];
    __shared__ int sbs[NB + 1];
    __shared__ int s_bmn, s_bmx, s_lo, s_hi;

    int nbq = (P1 + TQ - 1) / TQ;
    int n = blockIdx.x / nbq;
    int qs = (blockIdx.x - n * nbq) * TQ + threadIdx.x;   // sorted query slot
    int L1 = len1[n];
    if ((blockIdx.x - n * nbq) * TQ >= L1) return;        // whole block padded

    if (threadIdx.x == 0) { s_bmn = NB; s_bmx = -1; }
    for (int b = threadIdx.x; b <= NB; b += TQ)
        sbs[b] = g_bstart[n * (NB + 1) + b];
    __syncthreads();

    bool active = (qs < L1);
    float x1, y1, z1, s1;
    int i = 0;
    float zmin = g_zmin[n], inv = g_inv[n], w = g_w[n];
    if (active) {
        i = g_qidx[n * MAXP + qs];
        const float* p = p1 + ((size_t)n * P1 + i) * 3;
        x1 = p[0]; y1 = p[1]; z1 = p[2];
        s1 = sumsq_ref(x1, y1, z1);
        int b1 = zbin(z1, zmin, inv);
        atomicMin(&s_bmn, b1);
        atomicMax(&s_bmx, b1);
    } else {
        x1 = y1 = z1 = s1 = __int_as_float(0x7fffffff);   // NaN: never inserts
    }
    __syncthreads();

    // Initial window by count (tid 0).
    if (threadIdx.x == 0) {
        int lo = s_bmn, hi = s_bmx;
        bool side = true;
        while (sbs[hi + 1] - sbs[lo] < C0) {
            bool canR = (hi < NB - 1), canL = (lo > 0);
            if (!canR && !canL) break;
            if ((side && canR) || !canL) hi++; else lo--;
            side = !side;
        }
        s_lo = lo; s_hi = hi;
    }
    __syncthreads();
    int lo = s_lo, hi = s_hi;

    const float4* pk = g_pack + (size_t)n * MAXP;
    const int* tix = g_tidx + (size_t)n * MAXP;

    float best[KNN_K];
    int bi[KNN_K];
#pragma unroll
    for (int k = 0; k < KNN_K; k++) {
        best[k] = __int_as_float(0x7f800000);
        bi[k] = 0x7fffffff;
    }

    SCAN_RANGE(sbs[lo], sbs[hi + 1]);

    // Exact completeness: extend until every active thread's z-slab bound
    // exceeds its current 16th distance (+eps covers fp rounding of d).
    const float eps = 1e-4f;
    while (true) {
        bool needR = false, needL = false;
        if (active) {
            float b15 = best[KNN_K - 1];
            if (hi < NB - 1) {
                float dz = fmaxf(zmin + (float)(hi + 1) * w - z1, 0.0f);
                needR = (dz * dz <= b15 + eps);
            }
            if (lo > 0) {
                float dz = fmaxf(z1 - (zmin + (float)lo * w), 0.0f);
                needL = (dz * dz <= b15 + eps);
            }
        }
        int nr = __syncthreads_or((int)needR);
        int nl = __syncthreads_or((int)needL);
        if (!nr && !nl) break;
        if (nr) { SCAN_RANGE(sbs[hi + 1], sbs[hi + 2]); hi++; }
        if (nl) { SCAN_RANGE(sbs[lo - 1], sbs[lo]); lo--; }
    }

    if (active) {
        long long o = ((long long)n * P1 + i) * KNN_K;
#pragma unroll
        for (int k = 0; k < KNN_K; k++) {
            out[o + k] = (float)bi[k];
            out[NPK + o + k] = best[k];
        }
    }
}

extern "C" void kernel_launch(void* const* d_in, const int* in_sizes, int n_in,
                              void* d_out, int out_size) {
    const float* pts[2] = {0, 0};
    const int* lens[2] = {0, 0};
    int lsz[2] = {0, 0};
    int psz[2] = {0, 0};
    int npts = 0, nlen = 0;
    for (int i = 0; i < n_in; i++) {
        if (in_sizes[i] <= 1024) {
            if (nlen < 2) { lens[nlen] = (const int*)d_in[i]; lsz[nlen] = in_sizes[i]; nlen++; }
        } else {
            if (npts < 2) { pts[npts] = (const float*)d_in[i]; psz[npts] = in_sizes[i]; npts++; }
        }
    }
    const float* p1 = pts[0];
    const float* p2 = pts[1];
    const int* l1 = lens[0];
    const int* l2 = lens[1];

    int Nn = lsz[0];
    int P1 = psz[0] / (3 * Nn);
    int P2 = psz[1] / (3 * Nn);
    long long NPK = (long long)out_size / 2;   // first half idx, second half dists

    setup_kernel<<<Nn, 256>>>(p1, p2, l1, l2, P1, P2);

    int P = (P1 > P2) ? P1 : P2;
    scatter_kernel<<<(Nn * P + 255) / 256, 256>>>(p1, p2, l1, l2, Nn, P1, P2);

    zero_kernel<<<512, 256>>>((float*)d_out, (long long)out_size);

    int nbq = (P1 + TQ - 1) / TQ;
    knn_kernel<<<Nn * nbq, TQ>>>(p1, l1, (float*)d_out, Nn, P1, P2, NPK);
}

// round 7
// speedup vs baseline: 3.9211x; 1.1448x over previous
#include <cuda_runtime.h>

#define KNN_K 16
#define NB    128      // z bins per batch
#define TQ    64       // threads per query block
#define CH    768      // SMEM chunk (candidates)
#define C0    768      // initial window target count
#define BUF   8        // per-lane accept buffer
#define MAXN  8
#define MAXP  8192

// Static scratch (allocations are forbidden).
__device__ float4 g_pack[MAXN * MAXP];      // bin-sorted targets (x,y,z,||p||^2)
__device__ int    g_tidx[MAXN * MAXP];      // original target index
__device__ int    g_qidx[MAXN * MAXP];      // bin-sorted query original index
__device__ int    g_bstart[MAXN * (NB + 1)];
__device__ int    g_cnt[MAXN * NB];
__device__ int    g_qcnt[MAXN * NB];
__device__ float  g_zmin[MAXN], g_inv[MAXN], g_w[MAXN];

// ||p||^2 with reference rounding: rn(rn(x*x + y*y) + z*z), products rounded.
__device__ __forceinline__ float sumsq_ref(float x, float y, float z) {
    return __fadd_rn(__fadd_rn(__fmul_rn(x, x), __fmul_rn(y, y)),
                     __fmul_rn(z, z));
}

__device__ __forceinline__ int zbin(float z, float zmin, float inv) {
    int b = (int)((z - zmin) * inv);
    return min(NB - 1, max(0, b));
}

__global__ void setup_kernel(const float* __restrict__ p1,
                             const float* __restrict__ p2,
                             const int* __restrict__ len1,
                             const int* __restrict__ len2,
                             int P1, int P2) {
    int n = blockIdx.x, tid = threadIdx.x;
    int L1 = len1[n], L2 = len2[n];
    __shared__ float sred[256];
    __shared__ int hist[NB], qh[NB];

    float mn = 1e30f, mx = -1e30f;
    for (int j = tid; j < L2; j += 256) {
        float z = p2[((size_t)n * P2 + j) * 3 + 2];
        mn = fminf(mn, z); mx = fmaxf(mx, z);
    }
    sred[tid] = mn; __syncthreads();
    for (int s = 128; s > 0; s >>= 1) {
        if (tid < s) sred[tid] = fminf(sred[tid], sred[tid + s]);
        __syncthreads();
    }
    float zmin = sred[0]; __syncthreads();
    sred[tid] = mx; __syncthreads();
    for (int s = 128; s > 0; s >>= 1) {
        if (tid < s) sred[tid] = fmaxf(sred[tid], sred[tid + s]);
        __syncthreads();
    }
    float zmax = sred[0]; __syncthreads();

    float range = fmaxf(zmax - zmin, 1e-20f);
    float w = range / NB;
    float inv = (float)NB / range;
    if (tid == 0) { g_zmin[n] = zmin; g_inv[n] = inv; g_w[n] = w; }

    for (int b = tid; b < NB; b += 256) { hist[b] = 0; qh[b] = 0; }
    __syncthreads();
    for (int j = tid; j < L2; j += 256) {
        float z = p2[((size_t)n * P2 + j) * 3 + 2];
        atomicAdd(&hist[zbin(z, zmin, inv)], 1);
    }
    for (int j = tid; j < L1; j += 256) {
        float z = p1[((size_t)n * P1 + j) * 3 + 2];
        atomicAdd(&qh[zbin(z, zmin, inv)], 1);
    }
    __syncthreads();
    if (tid == 0) {
        int acc = 0;
        for (int b = 0; b < NB; b++) {
            g_bstart[n * (NB + 1) + b] = acc;
            g_cnt[n * NB + b] = acc;
            acc += hist[b];
        }
        g_bstart[n * (NB + 1) + NB] = acc;
        int qa = 0;
        for (int b = 0; b < NB; b++) { g_qcnt[n * NB + b] = qa; qa += qh[b]; }
    }
}

__global__ void scatter_kernel(const float* __restrict__ p1,
                               const float* __restrict__ p2,
                               const int* __restrict__ len1,
                               const int* __restrict__ len2,
                               int Nn, int P1, int P2) {
    int t = blockIdx.x * blockDim.x + threadIdx.x;
    int P = max(P1, P2);
    if (t >= Nn * P) return;
    int n = t / P;
    int j = t - n * P;
    float zmin = g_zmin[n], inv = g_inv[n];
    if (j < P2 && j < len2[n]) {
        const float* p = p2 + ((size_t)n * P2 + j) * 3;
        float x = p[0], y = p[1], z = p[2];
        int b = zbin(z, zmin, inv);
        int pos = atomicAdd(&g_cnt[n * NB + b], 1);
        g_pack[n * MAXP + pos] = make_float4(x, y, z, sumsq_ref(x, y, z));
        g_tidx[n * MAXP + pos] = j;
    }
    if (j < P1 && j < len1[n]) {
        float z = p1[((size_t)n * P1 + j) * 3 + 2];
        int b = zbin(z, zmin, inv);
        int pos = atomicAdd(&g_qcnt[n * NB + b], 1);
        g_qidx[n * MAXP + pos] = j;
    }
}

__global__ void zero_kernel(float* __restrict__ out, long long total) {
    long long t = (long long)blockIdx.x * blockDim.x + threadIdx.x;
    long long stride = (long long)gridDim.x * blockDim.x;
    for (; t < total; t += stride) out[t] = 0.0f;
}

#define LEX_LT(da, ia, db, ib) (((da) < (db)) || (((da) == (db)) && ((ia) < (ib))))

// Compare-exchange (ascending) on buffer arrays; static indices only.
#define CEB(a, b)                                                              \
    {                                                                          \
        bool c = LEX_LT(bd[b], bj[b], bd[a], bj[a]);                           \
        float tf = bd[a]; int ti = bj[a];                                      \
        bd[a] = c ? bd[b] : bd[a]; bj[a] = c ? bj[b] : bj[a];                  \
        bd[b] = c ? tf : bd[b];    bj[b] = c ? ti : bj[b];                     \
    }
// Compare-exchange on best list.
#define CEL(a, b)                                                              \
    {                                                                          \
        bool c = LEX_LT(best[b], bi[b], best[a], bi[a]);                       \
        float tf = best[a]; int ti = bi[a];                                    \
        best[a] = c ? best[b] : best[a]; bi[a] = c ? bi[b] : bi[a];            \
        best[b] = c ? tf : best[b];      bi[b] = c ? ti : bi[b];               \
    }

// Batcher odd-even sort-8 on (bd,bj). Unused slots hold (+inf, INT_MAX).
#define SORT8()                                                                \
    { CEB(0,1) CEB(2,3) CEB(4,5) CEB(6,7)                                      \
      CEB(0,2) CEB(1,3) CEB(4,6) CEB(5,7)                                      \
      CEB(1,2) CEB(5,6)                                                        \
      CEB(0,4) CEB(1,5) CEB(2,6) CEB(3,7)                                      \
      CEB(2,4) CEB(3,5)                                                        \
      CEB(1,2) CEB(3,4) CEB(5,6) }

// Collective flush: sort buffer, min-merge into best[8..15] (half-cleaner),
// then bitonic-16 merge. All static indices; no data-dependent branches.
#define FLUSH()                                                                \
    {                                                                          \
        SORT8();                                                               \
        _Pragma("unroll")                                                      \
        for (int s = 0; s < 8; s++) {                                          \
            int ii = 8 + s, rb = 7 - s;                                        \
            bool c = LEX_LT(bd[rb], bj[rb], best[ii], bi[ii]);                 \
            best[ii] = c ? bd[rb] : best[ii];                                  \
            bi[ii]   = c ? bj[rb] : bi[ii];                                    \
        }                                                                      \
        CEL(0,8) CEL(1,9) CEL(2,10) CEL(3,11)                                  \
        CEL(4,12) CEL(5,13) CEL(6,14) CEL(7,15)                                \
        CEL(0,4) CEL(1,5) CEL(2,6) CEL(3,7)                                    \
        CEL(8,12) CEL(9,13) CEL(10,14) CEL(11,15)                              \
        CEL(0,2) CEL(1,3) CEL(4,6) CEL(5,7)                                    \
        CEL(8,10) CEL(9,11) CEL(12,14) CEL(13,15)                              \
        CEL(0,1) CEL(2,3) CEL(4,5) CEL(6,7)                                    \
        CEL(8,9) CEL(10,11) CEL(12,13) CEL(14,15)                              \
        _Pragma("unroll")                                                      \
        for (int s = 0; s < BUF; s++) {                                        \
            bd[s] = __int_as_float(0x7f800000); bj[s] = 0x7fffffff;            \
        }                                                                      \
        cnt = 0;                                                               \
    }

__global__ __launch_bounds__(TQ) void knn_kernel(
    const float* __restrict__ p1,
    const int* __restrict__ len1,
    float* __restrict__ out,
    int Nn, int P1, int P2, long long NPK) {

    __shared__ float4 sh4[CH];
    __shared__ int shi[CH];
    __shared__ int sbs[NB + 1];
    __shared__ int s_bmn, s_bmx, s_lo, s_hi;

    int nbq = (P1 + TQ - 1) / TQ;
    int n = blockIdx.x / nbq;
    int qs = (blockIdx.x - n * nbq) * TQ + threadIdx.x;   // sorted query slot
    int L1 = len1[n];
    if ((blockIdx.x - n * nbq) * TQ >= L1) return;        // whole block padded

    if (threadIdx.x == 0) { s_bmn = NB; s_bmx = -1; }
    for (int b = threadIdx.x; b <= NB; b += TQ)
        sbs[b] = g_bstart[n * (NB + 1) + b];
    __syncthreads();

    bool active = (qs < L1);
    float x1, y1, z1, s1;
    int i = 0;
    float zmin = g_zmin[n], inv = g_inv[n], w = g_w[n];
    if (active) {
        i = g_qidx[n * MAXP + qs];
        const float* p = p1 + ((size_t)n * P1 + i) * 3;
        x1 = p[0]; y1 = p[1]; z1 = p[2];
        s1 = sumsq_ref(x1, y1, z1);
        int b1 = zbin(z1, zmin, inv);
        atomicMin(&s_bmn, b1);
        atomicMax(&s_bmx, b1);
    } else {
        x1 = y1 = z1 = s1 = __int_as_float(0x7fffffff);   // NaN: never accepts
    }
    __syncthreads();

    if (threadIdx.x == 0) {
        int lo = s_bmn, hi = s_bmx;
        bool side = true;
        while (sbs[hi + 1] - sbs[lo] < C0) {
            bool canR = (hi < NB - 1), canL = (lo > 0);
            if (!canR && !canL) break;
            if ((side && canR) || !canL) hi++; else lo--;
            side = !side;
        }
        s_lo = lo; s_hi = hi;
    }
    __syncthreads();
    int lo = s_lo, hi = s_hi;

    const float4* pk = g_pack + (size_t)n * MAXP;
    const int* tix = g_tidx + (size_t)n * MAXP;

    float best[KNN_K]; int bi[KNN_K];
    float bd[BUF]; int bj[BUF];
    int cnt = 0;
#pragma unroll
    for (int k = 0; k < KNN_K; k++) {
        best[k] = __int_as_float(0x7f800000);
        bi[k] = 0x7fffffff;
    }
#pragma unroll
    for (int s = 0; s < BUF; s++) {
        bd[s] = __int_as_float(0x7f800000); bj[s] = 0x7fffffff;
    }

    // Unified scan loop: first the initial window, then one bin per round
    // as demanded by the exact completeness check.
    int from = sbs[lo], to = sbs[hi + 1];
    const float eps = 1e-4f;
    while (true) {
        for (int base = from; base < to; base += CH) {
            int m = min(CH, to - base);
            __syncthreads();
            for (int t = threadIdx.x; t < m; t += TQ) {
                sh4[t] = __ldg(&pk[base + t]);
                shi[t] = __ldg(&tix[base + t]);
            }
            __syncthreads();
#pragma unroll 2
            for (int t = 0; t < m; ++t) {
                float4 q = sh4[t];
                float dot = __fmaf_rn(z1, q.z,
                            __fmaf_rn(y1, q.y,
                            __fmul_rn(x1, q.x)));
                float d = __fmaf_rn(-2.0f, dot, __fadd_rn(s1, q.w));
                bool acc = false;
                int jj = 0;
                if (d <= best[KNN_K - 1]) {
                    jj = shi[t];
                    acc = LEX_LT(d, jj, best[KNN_K - 1], bi[KNN_K - 1]);
                }
                if (acc) {
#pragma unroll
                    for (int s = 0; s < BUF; s++)
                        if (cnt == s) { bd[s] = d; bj[s] = jj; }
                    cnt++;
                }
                if (__any_sync(0xffffffffu, cnt == BUF)) FLUSH();
            }
        }
        FLUSH();   // fresh best[15] for the completeness bound

        bool needR = false, needL = false;
        if (active) {
            float b15 = best[KNN_K - 1];
            if (hi < NB - 1) {
                float dz = fmaxf(zmin + (float)(hi + 1) * w - z1, 0.0f);
                needR = (dz * dz <= b15 + eps);
            }
            if (lo > 0) {
                float dz = fmaxf(z1 - (zmin + (float)lo * w), 0.0f);
                needL = (dz * dz <= b15 + eps);
            }
        }
        int nr = __syncthreads_or((int)needR);
        int nl = __syncthreads_or((int)needL);
        if (nr)      { from = sbs[hi + 1]; to = sbs[hi + 2]; hi++; }
        else if (nl) { from = sbs[lo - 1]; to = sbs[lo];     lo--; }
        else break;
    }

    if (active) {
        long long o = ((long long)n * P1 + i) * KNN_K;
#pragma unroll
        for (int k = 0; k < KNN_K; k++) {
            out[o + k] = (float)bi[k];
            out[NPK + o + k] = best[k];
        }
    }
}

extern "C" void kernel_launch(void* const* d_in, const int* in_sizes, int n_in,
                              void* d_out, int out_size) {
    const float* pts[2] = {0, 0};
    const int* lens[2] = {0, 0};
    int lsz[2] = {0, 0};
    int psz[2] = {0, 0};
    int npts = 0, nlen = 0;
    for (int i = 0; i < n_in; i++) {
        if (in_sizes[i] <= 1024) {
            if (nlen < 2) { lens[nlen] = (const int*)d_in[i]; lsz[nlen] = in_sizes[i]; nlen++; }
        } else {
            if (npts < 2) { pts[npts] = (const float*)d_in[i]; psz[npts] = in_sizes[i]; npts++; }
        }
    }
    const float* p1 = pts[0];
    const float* p2 = pts[1];
    const int* l1 = lens[0];
    const int* l2 = lens[1];

    int Nn = lsz[0];
    int P1 = psz[0] / (3 * Nn);
    int P2 = psz[1] / (3 * Nn);
    long long NPK = (long long)out_size / 2;   // first half idx, second half dists

    setup_kernel<<<Nn, 256>>>(p1, p2, l1, l2, P1, P2);

    int P = (P1 > P2) ? P1 : P2;
    scatter_kernel<<<(Nn * P + 255) / 256, 256>>>(p1, p2, l1, l2, Nn, P1, P2);

    zero_kernel<<<512, 256>>>((float*)d_out, (long long)out_size);

    int nbq = (P1 + TQ - 1) / TQ;
    knn_kernel<<<Nn * nbq, TQ>>>(p1, l1, (float*)d_out, Nn, P1, P2, NPK);
}

// round 8
// speedup vs baseline: 14.1654x; 3.6126x over previous
#include <cuda_runtime.h>

#define KNN_K 16
#define NB    128      // z bins per batch
#define C0    192      // initial per-query window candidate count
#define MAXN  8
#define MAXP  8192
#define FULLM 0xffffffffu

// Static scratch (allocations are forbidden).
__device__ float4 g_pack[MAXN * MAXP];      // bin-sorted targets (x,y,z,||p||^2)
__device__ int    g_tidx[MAXN * MAXP];      // original target index
__device__ int    g_qidx[MAXN * MAXP];      // bin-sorted query original index
__device__ int    g_bstart[MAXN * (NB + 1)];
__device__ int    g_cnt[MAXN * NB];
__device__ int    g_qcnt[MAXN * NB];
__device__ float  g_zmin[MAXN], g_inv[MAXN], g_w[MAXN];

// ||p||^2 with reference rounding: rn(rn(x*x + y*y) + z*z), products rounded.
__device__ __forceinline__ float sumsq_ref(float x, float y, float z) {
    return __fadd_rn(__fadd_rn(__fmul_rn(x, x), __fmul_rn(y, y)),
                     __fmul_rn(z, z));
}

__device__ __forceinline__ int zbin(float z, float zmin, float inv) {
    int b = (int)((z - zmin) * inv);
    return min(NB - 1, max(0, b));
}

__global__ void setup_kernel(const float* __restrict__ p1,
                             const float* __restrict__ p2,
                             const int* __restrict__ len1,
                             const int* __restrict__ len2,
                             int P1, int P2) {
    int n = blockIdx.x, tid = threadIdx.x;
    int L1 = len1[n], L2 = len2[n];
    __shared__ float sred[256];
    __shared__ int hist[NB], qh[NB];

    float mn = 1e30f, mx = -1e30f;
    for (int j = tid; j < L2; j += 256) {
        float z = p2[((size_t)n * P2 + j) * 3 + 2];
        mn = fminf(mn, z); mx = fmaxf(mx, z);
    }
    sred[tid] = mn; __syncthreads();
    for (int s = 128; s > 0; s >>= 1) {
        if (tid < s) sred[tid] = fminf(sred[tid], sred[tid + s]);
        __syncthreads();
    }
    float zmin = sred[0]; __syncthreads();
    sred[tid] = mx; __syncthreads();
    for (int s = 128; s > 0; s >>= 1) {
        if (tid < s) sred[tid] = fmaxf(sred[tid], sred[tid + s]);
        __syncthreads();
    }
    float zmax = sred[0]; __syncthreads();

    float range = fmaxf(zmax - zmin, 1e-20f);
    float w = range / NB;
    float inv = (float)NB / range;
    if (tid == 0) { g_zmin[n] = zmin; g_inv[n] = inv; g_w[n] = w; }

    for (int b = tid; b < NB; b += 256) { hist[b] = 0; qh[b] = 0; }
    __syncthreads();
    for (int j = tid; j < L2; j += 256) {
        float z = p2[((size_t)n * P2 + j) * 3 + 2];
        atomicAdd(&hist[zbin(z, zmin, inv)], 1);
    }
    for (int j = tid; j < L1; j += 256) {
        float z = p1[((size_t)n * P1 + j) * 3 + 2];
        atomicAdd(&qh[zbin(z, zmin, inv)], 1);
    }
    __syncthreads();
    if (tid == 0) {
        int acc = 0;
        for (int b = 0; b < NB; b++) {
            g_bstart[n * (NB + 1) + b] = acc;
            g_cnt[n * NB + b] = acc;
            acc += hist[b];
        }
        g_bstart[n * (NB + 1) + NB] = acc;
        int qa = 0;
        for (int b = 0; b < NB; b++) { g_qcnt[n * NB + b] = qa; qa += qh[b]; }
    }
}

__global__ void scatter_kernel(const float* __restrict__ p1,
                               const float* __restrict__ p2,
                               const int* __restrict__ len1,
                               const int* __restrict__ len2,
                               int Nn, int P1, int P2) {
    int t = blockIdx.x * blockDim.x + threadIdx.x;
    int P = max(P1, P2);
    if (t >= Nn * P) return;
    int n = t / P;
    int j = t - n * P;
    float zmin = g_zmin[n], inv = g_inv[n];
    if (j < P2 && j < len2[n]) {
        const float* p = p2 + ((size_t)n * P2 + j) * 3;
        float x = p[0], y = p[1], z = p[2];
        int b = zbin(z, zmin, inv);
        int pos = atomicAdd(&g_cnt[n * NB + b], 1);
        g_pack[n * MAXP + pos] = make_float4(x, y, z, sumsq_ref(x, y, z));
        g_tidx[n * MAXP + pos] = j;
    }
    if (j < P1 && j < len1[n]) {
        float z = p1[((size_t)n * P1 + j) * 3 + 2];
        int b = zbin(z, zmin, inv);
        int pos = atomicAdd(&g_qcnt[n * NB + b], 1);
        g_qidx[n * MAXP + pos] = j;
    }
}

__global__ void zero_kernel(float* __restrict__ out, long long total) {
    long long t = (long long)blockIdx.x * blockDim.x + threadIdx.x;
    long long stride = (long long)gridDim.x * blockDim.x;
    for (; t < total; t += stride) out[t] = 0.0f;
}

#define LEX_LT(da, ia, db, ib) (((da) < (db)) || (((da) == (db)) && ((ia) < (ib))))

// Warp-distributed sorted top list: lane k holds k-th smallest (lex on (d,idx));
// lanes 16..31 are sorted overflow. One warp per query.
__global__ __launch_bounds__(256) void knn_kernel(
    const float* __restrict__ p1,
    const int* __restrict__ len1,
    float* __restrict__ out,
    int Nn, int P1, int P2, long long NPK) {

    int gw = (blockIdx.x * blockDim.x + threadIdx.x) >> 5;   // global warp id
    int lane = threadIdx.x & 31;
    if (gw >= Nn * P1) return;
    int n = gw / P1;
    int qs = gw - n * P1;                                    // sorted query slot
    int L1 = __ldg(&len1[n]);
    if (qs >= L1) return;                                    // zeros pre-written

    int i = __ldg(&g_qidx[n * MAXP + qs]);                   // original query idx
    const float* p = p1 + ((size_t)n * P1 + i) * 3;
    float x1 = __ldg(&p[0]), y1 = __ldg(&p[1]), z1 = __ldg(&p[2]);
    float s1 = sumsq_ref(x1, y1, z1);

    float zmin = g_zmin[n], inv = g_inv[n], w = g_w[n];
    const float4* pk = g_pack + (size_t)n * MAXP;
    const int* tix = g_tidx + (size_t)n * MAXP;
    const int* bs = g_bstart + n * (NB + 1);

    // Initial window by count around the query's bin (warp-uniform values).
    int b1 = zbin(z1, zmin, inv);
    int lo = b1, hi = b1;
    {
        int cstart = __ldg(&bs[lo]), cend = __ldg(&bs[hi + 1]);
        bool side = true;
        while (cend - cstart < C0) {
            bool canR = (hi < NB - 1), canL = (lo > 0);
            if (!canR && !canL) break;
            if ((side && canR) || !canL) { hi++; cend = __ldg(&bs[hi + 1]); }
            else { lo--; cstart = __ldg(&bs[lo]); }
            side = !side;
        }
    }

    // Distributed list: this lane's element.
    float ld = __int_as_float(0x7f800000);
    int   lj = 0x7fffffff;
    float b15d = ld; int b15j = lj;

    int from = __ldg(&bs[lo]), to = __ldg(&bs[hi + 1]);
    const float eps = 1e-4f;

    while (true) {
        for (int base = from; base < to; base += 32) {
            int t = base + lane;
            float d; int jj;
            if (t < to) {
                float4 q = __ldg(&pk[t]);
                float dot = __fmaf_rn(z1, q.z,
                            __fmaf_rn(y1, q.y,
                            __fmul_rn(x1, q.x)));
                d = __fmaf_rn(-2.0f, dot, __fadd_rn(s1, q.w));
                jj = __ldg(&tix[t]);
            } else {
                d = __int_as_float(0x7f800000);
                jj = 0x7fffffff;
            }
            bool acc = LEX_LT(d, jj, b15d, b15j);
            unsigned am = __ballot_sync(FULLM, acc);
            while (am) {
                int src = __ffs(am) - 1;
                am &= am - 1;
                float cd = __shfl_sync(FULLM, d, src);
                int   cj = __shfl_sync(FULLM, jj, src);
                float pd = __shfl_up_sync(FULLM, ld, 1);
                int   pj = __shfl_up_sync(FULLM, lj, 1);
                if (LEX_LT(cd, cj, ld, lj)) {
                    // cand displaces from my slot: take cand if it lands here,
                    // else take my predecessor's old element (shift down).
                    bool here = (lane == 0) || LEX_LT(pd, pj, cd, cj);
                    ld = here ? cd : pd;
                    lj = here ? cj : pj;
                }
            }
            b15d = __shfl_sync(FULLM, ld, 15);
            b15j = __shfl_sync(FULLM, lj, 15);
        }

        // Exact completeness (warp-uniform): extend while the z-slab bound
        // can still contain a better 16th (+eps covers fp rounding of d).
        bool needR = false, needL = false;
        if (hi < NB - 1) {
            float dz = fmaxf(zmin + (float)(hi + 1) * w - z1, 0.0f);
            needR = (dz * dz <= b15d + eps);
        }
        if (lo > 0) {
            float dz = fmaxf(z1 - (zmin + (float)lo * w), 0.0f);
            needL = (dz * dz <= b15d + eps);
        }
        if (needR)      { from = __ldg(&bs[hi + 1]); to = __ldg(&bs[hi + 2]); hi++; }
        else if (needL) { from = __ldg(&bs[lo - 1]); to = __ldg(&bs[lo]);     lo--; }
        else break;
    }

    if (lane < KNN_K) {
        long long o = ((long long)n * P1 + i) * KNN_K;
        out[o + lane] = (float)lj;
        out[NPK + o + lane] = ld;
    }
}

extern "C" void kernel_launch(void* const* d_in, const int* in_sizes, int n_in,
                              void* d_out, int out_size) {
    const float* pts[2] = {0, 0};
    const int* lens[2] = {0, 0};
    int lsz[2] = {0, 0};
    int psz[2] = {0, 0};
    int npts = 0, nlen = 0;
    for (int i = 0; i < n_in; i++) {
        if (in_sizes[i] <= 1024) {
            if (nlen < 2) { lens[nlen] = (const int*)d_in[i]; lsz[nlen] = in_sizes[i]; nlen++; }
        } else {
            if (npts < 2) { pts[npts] = (const float*)d_in[i]; psz[npts] = in_sizes[i]; npts++; }
        }
    }
    const float* p1 = pts[0];
    const float* p2 = pts[1];
    const int* l1 = lens[0];
    const int* l2 = lens[1];

    int Nn = lsz[0];
    int P1 = psz[0] / (3 * Nn);
    int P2 = psz[1] / (3 * Nn);
    long long NPK = (long long)out_size / 2;   // first half idx, second half dists

    setup_kernel<<<Nn, 256>>>(p1, p2, l1, l2, P1, P2);

    int P = (P1 > P2) ? P1 : P2;
    scatter_kernel<<<(Nn * P + 255) / 256, 256>>>(p1, p2, l1, l2, Nn, P1, P2);

    zero_kernel<<<512, 256>>>((float*)d_out, (long long)out_size);

    long long threads = (long long)Nn * P1 * 32;
    int blocks = (int)((threads + 255) / 256);
    knn_kernel<<<blocks, 256>>>(p1, l1, (float*)d_out, Nn, P1, P2, NPK);
}

// round 9
// speedup vs baseline: 15.1823x; 1.0718x over previous
#include <cuda_runtime.h>

#define KNN_K 16
#define NB    128      // z bins per batch
#define C0    192      // initial per-query window candidate count
#define MAXN  8
#define MAXP  8192
#define FULLM 0xffffffffu

// Static scratch (allocations are forbidden).
__device__ float4 g_pack[MAXN * MAXP];      // bin-sorted targets (x,y,z,idx-as-float-bits)
__device__ int    g_qidx[MAXN * MAXP];      // bin-sorted query original index
__device__ int    g_bstart[MAXN * (NB + 1)];
__device__ int    g_cnt[MAXN * NB];
__device__ int    g_qcnt[MAXN * NB];
__device__ float  g_zmin[MAXN], g_inv[MAXN], g_w[MAXN];

// ||p||^2 with reference rounding: rn(rn(x*x + y*y) + z*z), products rounded.
__device__ __forceinline__ float sumsq_ref(float x, float y, float z) {
    return __fadd_rn(__fadd_rn(__fmul_rn(x, x), __fmul_rn(y, y)),
                     __fmul_rn(z, z));
}

__device__ __forceinline__ int zbin(float z, float zmin, float inv) {
    int b = (int)((z - zmin) * inv);
    return min(NB - 1, max(0, b));
}

__global__ void setup_kernel(const float* __restrict__ p1,
                             const float* __restrict__ p2,
                             const int* __restrict__ len1,
                             const int* __restrict__ len2,
                             int P1, int P2) {
    int n = blockIdx.x, tid = threadIdx.x;
    int L1 = len1[n], L2 = len2[n];
    __shared__ float sred[256];
    __shared__ int hist[NB], qh[NB];

    float mn = 1e30f, mx = -1e30f;
    for (int j = tid; j < L2; j += 256) {
        float z = p2[((size_t)n * P2 + j) * 3 + 2];
        mn = fminf(mn, z); mx = fmaxf(mx, z);
    }
    sred[tid] = mn; __syncthreads();
    for (int s = 128; s > 0; s >>= 1) {
        if (tid < s) sred[tid] = fminf(sred[tid], sred[tid + s]);
        __syncthreads();
    }
    float zmin = sred[0]; __syncthreads();
    sred[tid] = mx; __syncthreads();
    for (int s = 128; s > 0; s >>= 1) {
        if (tid < s) sred[tid] = fmaxf(sred[tid], sred[tid + s]);
        __syncthreads();
    }
    float zmax = sred[0]; __syncthreads();

    float range = fmaxf(zmax - zmin, 1e-20f);
    float w = range / NB;
    float inv = (float)NB / range;
    if (tid == 0) { g_zmin[n] = zmin; g_inv[n] = inv; g_w[n] = w; }

    for (int b = tid; b < NB; b += 256) { hist[b] = 0; qh[b] = 0; }
    __syncthreads();
    for (int j = tid; j < L2; j += 256) {
        float z = p2[((size_t)n * P2 + j) * 3 + 2];
        atomicAdd(&hist[zbin(z, zmin, inv)], 1);
    }
    for (int j = tid; j < L1; j += 256) {
        float z = p1[((size_t)n * P1 + j) * 3 + 2];
        atomicAdd(&qh[zbin(z, zmin, inv)], 1);
    }
    __syncthreads();
    if (tid == 0) {
        int acc = 0;
        for (int b = 0; b < NB; b++) {
            g_bstart[n * (NB + 1) + b] = acc;
            g_cnt[n * NB + b] = acc;
            acc += hist[b];
        }
        g_bstart[n * (NB + 1) + NB] = acc;
        int qa = 0;
        for (int b = 0; b < NB; b++) { g_qcnt[n * NB + b] = qa; qa += qh[b]; }
    }
}

__global__ void scatter_kernel(const float* __restrict__ p1,
                               const float* __restrict__ p2,
                               const int* __restrict__ len1,
                               const int* __restrict__ len2,
                               int Nn, int P1, int P2) {
    int t = blockIdx.x * blockDim.x + threadIdx.x;
    int P = max(P1, P2);
    if (t >= Nn * P) return;
    int n = t / P;
    int j = t - n * P;
    float zmin = g_zmin[n], inv = g_inv[n];
    if (j < P2 && j < len2[n]) {
        const float* p = p2 + ((size_t)n * P2 + j) * 3;
        float x = p[0], y = p[1], z = p[2];
        int b = zbin(z, zmin, inv);
        int pos = atomicAdd(&g_cnt[n * NB + b], 1);
        g_pack[n * MAXP + pos] = make_float4(x, y, z, __int_as_float(j));
    }
    if (j < P1 && j < len1[n]) {
        float z = p1[((size_t)n * P1 + j) * 3 + 2];
        int b = zbin(z, zmin, inv);
        int pos = atomicAdd(&g_qcnt[n * NB + b], 1);
        g_qidx[n * MAXP + pos] = j;
    }
}

__global__ void zero_kernel(float* __restrict__ out, long long total) {
    long long t = (long long)blockIdx.x * blockDim.x + threadIdx.x;
    long long stride = (long long)gridDim.x * blockDim.x;
    for (; t < total; t += stride) out[t] = 0.0f;
}

#define LEX_LT(da, ia, db, ib) (((da) < (db)) || (((da) == (db)) && ((ia) < (ib))))

// Warp-distributed sorted top list: lane k holds k-th smallest (lex on (d,idx));
// lanes 16..31 are sorted overflow. One warp per query.
__global__ __launch_bounds__(256) void knn_kernel(
    const float* __restrict__ p1,
    const int* __restrict__ len1,
    float* __restrict__ out,
    int Nn, int P1, int P2, long long NPK) {

    int gw = (blockIdx.x * blockDim.x + threadIdx.x) >> 5;   // global warp id
    int lane = threadIdx.x & 31;
    if (gw >= Nn * P1) return;
    int n = gw / P1;
    int qs = gw - n * P1;                                    // sorted query slot
    int L1 = __ldg(&len1[n]);
    if (qs >= L1) return;                                    // zeros pre-written

    int i = __ldg(&g_qidx[n * MAXP + qs]);                   // original query idx
    const float* p = p1 + ((size_t)n * P1 + i) * 3;
    float x1 = __ldg(&p[0]), y1 = __ldg(&p[1]), z1 = __ldg(&p[2]);
    float s1 = sumsq_ref(x1, y1, z1);

    float zmin = g_zmin[n], inv = g_inv[n], w = g_w[n];
    const float4* pk = g_pack + (size_t)n * MAXP;
    const int* bs = g_bstart + n * (NB + 1);

    // Preload 32 bin boundaries around the query's bin into lane registers:
    // pv = bs[b1-15+lane]; later reads via shfl (no dependent-load chain).
    int b1 = zbin(z1, zmin, inv);
    int pbase = b1 - 15;
    int pb = min(max(pbase + lane, 0), NB);
    int pv = __ldg(&bs[pb]);

#define BS_GET(b) (((b) >= pbase && (b) < pbase + 32)                           \
                       ? __shfl_sync(FULLM, pv, (b) - pbase)                    \
                       : __ldg(&bs[(b)]))

    // Initial window by count (warp-uniform).
    int lo = b1, hi = b1;
    int from = BS_GET(lo), to = BS_GET(hi + 1);
    {
        bool side = true;
        while (to - from < C0) {
            bool canR = (hi < NB - 1), canL = (lo > 0);
            if (!canR && !canL) break;
            if ((side && canR) || !canL) { hi++; to = BS_GET(hi + 1); }
            else { lo--; from = BS_GET(lo); }
            side = !side;
        }
    }

    // First 32 candidates: compute + warp bitonic sort-32 initializes the list.
    float ld; int lj;
    {
        int t = from + lane;
        float d; int jj;
        if (t < to) {
            float4 q = __ldg(&pk[t]);
            float s2 = sumsq_ref(q.x, q.y, q.z);
            float dot = __fmaf_rn(z1, q.z,
                        __fmaf_rn(y1, q.y,
                        __fmul_rn(x1, q.x)));
            d = __fmaf_rn(-2.0f, dot, __fadd_rn(s1, s2));
            jj = __float_as_int(q.w);
        } else {
            d = __int_as_float(0x7f800000);
            jj = 0x7fffffff;
        }
#pragma unroll
        for (int k = 2; k <= 32; k <<= 1) {
#pragma unroll
            for (int j = k >> 1; j > 0; j >>= 1) {
                float od = __shfl_xor_sync(FULLM, d, j);
                int   oj = __shfl_xor_sync(FULLM, jj, j);
                bool up = ((lane & k) == 0);
                bool want_min = (((lane & j) == 0) == up);
                bool mine_lt = LEX_LT(d, jj, od, oj);
                bool take_other = (mine_lt != want_min);
                d  = take_other ? od : d;
                jj = take_other ? oj : jj;
            }
        }
        ld = d; lj = jj;
    }
    float b15d = __shfl_sync(FULLM, ld, 15);
    int   b15j = __shfl_sync(FULLM, lj, 15);

    int base0 = from + 32;
    const float eps = 1e-4f;

    while (true) {
        for (int base = base0; base < to; base += 32) {
            int t = base + lane;
            float d; int jj;
            if (t < to) {
                float4 q = __ldg(&pk[t]);
                float s2 = sumsq_ref(q.x, q.y, q.z);
                float dot = __fmaf_rn(z1, q.z,
                            __fmaf_rn(y1, q.y,
                            __fmul_rn(x1, q.x)));
                d = __fmaf_rn(-2.0f, dot, __fadd_rn(s1, s2));
                jj = __float_as_int(q.w);
            } else {
                d = __int_as_float(0x7f800000);
                jj = 0x7fffffff;
            }
            bool acc = LEX_LT(d, jj, b15d, b15j);
            unsigned am = __ballot_sync(FULLM, acc);
            while (am) {
                int src = __ffs(am) - 1;
                am &= am - 1;
                float cd = __shfl_sync(FULLM, d, src);
                int   cj = __shfl_sync(FULLM, jj, src);
                float pd = __shfl_up_sync(FULLM, ld, 1);
                int   pj = __shfl_up_sync(FULLM, lj, 1);
                if (LEX_LT(cd, cj, ld, lj)) {
                    bool here = (lane == 0) || LEX_LT(pd, pj, cd, cj);
                    ld = here ? cd : pd;
                    lj = here ? cj : pj;
                }
            }
            b15d = __shfl_sync(FULLM, ld, 15);
            b15j = __shfl_sync(FULLM, lj, 15);
        }

        // Exact completeness (warp-uniform): extend while the z-slab bound
        // can still contain a better 16th (+eps covers fp rounding of d).
        bool needR = false, needL = false;
        if (hi < NB - 1) {
            float dz = fmaxf(zmin + (float)(hi + 1) * w - z1, 0.0f);
            needR = (dz * dz <= b15d + eps);
        }
        if (lo > 0) {
            float dz = fmaxf(z1 - (zmin + (float)lo * w), 0.0f);
            needL = (dz * dz <= b15d + eps);
        }
        if (needR)      { base0 = BS_GET(hi + 1); to = BS_GET(hi + 2); hi++; }
        else if (needL) { base0 = BS_GET(lo - 1); to = BS_GET(lo);     lo--; }
        else break;
    }

    if (lane < KNN_K) {
        long long o = ((long long)n * P1 + i) * KNN_K;
        out[o + lane] = (float)lj;
        out[NPK + o + lane] = ld;
    }
}

extern "C" void kernel_launch(void* const* d_in, const int* in_sizes, int n_in,
                              void* d_out, int out_size) {
    const float* pts[2] = {0, 0};
    const int* lens[2] = {0, 0};
    int lsz[2] = {0, 0};
    int psz[2] = {0, 0};
    int npts = 0, nlen = 0;
    for (int i = 0; i < n_in; i++) {
        if (in_sizes[i] <= 1024) {
            if (nlen < 2) { lens[nlen] = (const int*)d_in[i]; lsz[nlen] = in_sizes[i]; nlen++; }
        } else {
            if (npts < 2) { pts[npts] = (const float*)d_in[i]; psz[npts] = in_sizes[i]; npts++; }
        }
    }
    const float* p1 = pts[0];
    const float* p2 = pts[1];
    const int* l1 = lens[0];
    const int* l2 = lens[1];

    int Nn = lsz[0];
    int P1 = psz[0] / (3 * Nn);
    int P2 = psz[1] / (3 * Nn);
    long long NPK = (long long)out_size / 2;   // first half idx, second half dists

    setup_kernel<<<Nn, 256>>>(p1, p2, l1, l2, P1, P2);

    int P = (P1 > P2) ? P1 : P2;
    scatter_kernel<<<(Nn * P + 255) / 256, 256>>>(p1, p2, l1, l2, Nn, P1, P2);

    zero_kernel<<<512, 256>>>((float*)d_out, (long long)out_size);

    long long threads = (long long)Nn * P1 * 32;
    int blocks = (int)((threads + 255) / 256);
    knn_kernel<<<blocks, 256>>>(p1, l1, (float*)d_out, Nn, P1, P2, NPK);
}

// round 10
// speedup vs baseline: 16.9645x; 1.1174x over previous
#include <cuda_runtime.h>

#define KNN_K 16
#define NBZ   64
#define NBY   64
#define NBB   (NBZ * NBY)
#define BW    10       // bootstrap y half-width (bins)
#define MAXN  8
#define MAXP  8192
#define FULLM 0xffffffffu
#define FINF  __int_as_float(0x7f800000)

// Static scratch (allocations are forbidden).
__device__ float4 g_pack[MAXN * MAXP];      // bin-sorted targets (x,y,z,idx-bits)
__device__ int    g_qidx[MAXN * MAXP];      // bin-sorted query original index
__device__ int    g_bstart[MAXN * (NBB + 1)];
__device__ int    g_cnt[MAXN * NBB];
__device__ int    g_qcnt[MAXN * NBB];
__device__ float  g_zmin[MAXN], g_invz[MAXN], g_wz[MAXN];
__device__ float  g_ymin[MAXN], g_invy[MAXN];

// ||p||^2 with reference rounding: rn(rn(x*x + y*y) + z*z), products rounded.
__device__ __forceinline__ float sumsq_ref(float x, float y, float z) {
    return __fadd_rn(__fadd_rn(__fmul_rn(x, x), __fmul_rn(y, y)),
                     __fmul_rn(z, z));
}

__device__ __forceinline__ int binof(float v, float vmin, float inv, int nb) {
    int b = (int)((v - vmin) * inv);
    return min(nb - 1, max(0, b));
}

__global__ void setup_kernel(const float* __restrict__ p1,
                             const float* __restrict__ p2,
                             const int* __restrict__ len1,
                             const int* __restrict__ len2,
                             int P1, int P2) {
    int n = blockIdx.x, tid = threadIdx.x;   // 256 threads
    int L1 = len1[n], L2 = len2[n];
    __shared__ int hist[NBB];
    __shared__ int qh[NBB];
    __shared__ float sred[256];
    __shared__ int part[256];

    float zmn = 1e30f, zmx = -1e30f, ymn = 1e30f, ymx = -1e30f;
    for (int j = tid; j < L2; j += 256) {
        const float* p = p2 + ((size_t)n * P2 + j) * 3;
        float y = p[1], z = p[2];
        zmn = fminf(zmn, z); zmx = fmaxf(zmx, z);
        ymn = fminf(ymn, y); ymx = fmaxf(ymx, y);
    }
#define REDUCE(var, op)                                                        \
    sred[tid] = var; __syncthreads();                                          \
    for (int s = 128; s > 0; s >>= 1) {                                        \
        if (tid < s) sred[tid] = op(sred[tid], sred[tid + s]);                 \
        __syncthreads();                                                       \
    }                                                                          \
    var = sred[0]; __syncthreads();
    REDUCE(zmn, fminf) REDUCE(zmx, fmaxf) REDUCE(ymn, fminf) REDUCE(ymx, fmaxf)
#undef REDUCE

    float rz = fmaxf(zmx - zmn, 1e-20f);
    float ry = fmaxf(ymx - ymn, 1e-20f);
    if (tid == 0) {
        g_zmin[n] = zmn; g_invz[n] = (float)NBZ / rz; g_wz[n] = rz / NBZ;
        g_ymin[n] = ymn; g_invy[n] = (float)NBY / ry;
    }
    float invz = (float)NBZ / rz, invy = (float)NBY / ry;

    for (int b = tid; b < NBB; b += 256) { hist[b] = 0; qh[b] = 0; }
    __syncthreads();
    for (int j = tid; j < L2; j += 256) {
        const float* p = p2 + ((size_t)n * P2 + j) * 3;
        int b = binof(p[2], zmn, invz, NBZ) * NBY + binof(p[1], ymn, invy, NBY);
        atomicAdd(&hist[b], 1);
    }
    for (int j = tid; j < L1; j += 256) {
        const float* p = p1 + ((size_t)n * P1 + j) * 3;
        int b = binof(p[2], zmn, invz, NBZ) * NBY + binof(p[1], ymn, invy, NBY);
        atomicAdd(&qh[b], 1);
    }
    __syncthreads();

    // Exclusive scan of hist -> g_bstart, g_cnt. NBB/256 = 16 bins per thread.
    {
        int base = tid * (NBB / 256);
        int s = 0;
        for (int k = 0; k < NBB / 256; k++) s += hist[base + k];
        part[tid] = s; __syncthreads();
        if (tid == 0) {
            int run = 0;
            for (int t = 0; t < 256; t++) { int v = part[t]; part[t] = run; run += v; }
        }
        __syncthreads();
        int run = part[tid];
        for (int k = 0; k < NBB / 256; k++) {
            int b = base + k;
            g_bstart[n * (NBB + 1) + b] = run;
            g_cnt[n * NBB + b] = run;
            run += hist[b];
        }
        if (tid == 255) g_bstart[n * (NBB + 1) + NBB] = run;
        __syncthreads();
    }
    // Exclusive scan of qh -> g_qcnt.
    {
        int base = tid * (NBB / 256);
        int s = 0;
        for (int k = 0; k < NBB / 256; k++) s += qh[base + k];
        part[tid] = s; __syncthreads();
        if (tid == 0) {
            int run = 0;
            for (int t = 0; t < 256; t++) { int v = part[t]; part[t] = run; run += v; }
        }
        __syncthreads();
        int run = part[tid];
        for (int k = 0; k < NBB / 256; k++) {
            int b = base + k;
            g_qcnt[n * NBB + b] = run;
            run += qh[b];
        }
    }
}

__global__ void scatter_kernel(const float* __restrict__ p1,
                               const float* __restrict__ p2,
                               const int* __restrict__ len1,
                               const int* __restrict__ len2,
                               int Nn, int P1, int P2) {
    int t = blockIdx.x * blockDim.x + threadIdx.x;
    int P = max(P1, P2);
    if (t >= Nn * P) return;
    int n = t / P;
    int j = t - n * P;
    float zmn = g_zmin[n], invz = g_invz[n];
    float ymn = g_ymin[n], invy = g_invy[n];
    if (j < P2 && j < len2[n]) {
        const float* p = p2 + ((size_t)n * P2 + j) * 3;
        float x = p[0], y = p[1], z = p[2];
        int b = binof(z, zmn, invz, NBZ) * NBY + binof(y, ymn, invy, NBY);
        int pos = atomicAdd(&g_cnt[n * NBB + b], 1);
        g_pack[n * MAXP + pos] = make_float4(x, y, z, __int_as_float(j));
    }
    if (j < P1 && j < len1[n]) {
        const float* p = p1 + ((size_t)n * P1 + j) * 3;
        int b = binof(p[2], zmn, invz, NBZ) * NBY + binof(p[1], ymn, invy, NBY);
        int pos = atomicAdd(&g_qcnt[n * NBB + b], 1);
        g_qidx[n * MAXP + pos] = j;
    }
}

__global__ void zero_kernel(float* __restrict__ out, long long total) {
    long long t = (long long)blockIdx.x * blockDim.x + threadIdx.x;
    long long stride = (long long)gridDim.x * blockDim.x;
    for (; t < total; t += stride) out[t] = 0.0f;
}

#define LEX_LT(da, ia, db, ib) (((da) < (db)) || (((da) == (db)) && ((ia) < (ib))))

// One warp per query; warp-distributed sorted top list (lane k = k-th best,
// lex on (d, idx); lanes 16..31 sorted overflow).
__global__ __launch_bounds__(256) void knn_kernel(
    const float* __restrict__ p1,
    const int* __restrict__ len1,
    float* __restrict__ out,
    int Nn, int P1, int P2, long long NPK) {

    int gw = (blockIdx.x * blockDim.x + threadIdx.x) >> 5;
    int lane = threadIdx.x & 31;
    if (gw >= Nn * P1) return;
    int n = gw / P1;
    int qs = gw - n * P1;
    int L1 = __ldg(&len1[n]);
    if (qs >= L1) return;                                    // zeros pre-written

    int i = __ldg(&g_qidx[n * MAXP + qs]);
    const float* p = p1 + ((size_t)n * P1 + i) * 3;
    float x1 = __ldg(&p[0]), y1 = __ldg(&p[1]), z1 = __ldg(&p[2]);
    float s1 = sumsq_ref(x1, y1, z1);

    float zmn = g_zmin[n], invz = g_invz[n], wz = g_wz[n];
    float ymn = g_ymin[n], invy = g_invy[n];
    const float4* pk = g_pack + (size_t)n * MAXP;
    const int* bs = g_bstart + n * (NBB + 1);

    int bz = binof(z1, zmn, invz, NBZ);
    int by = binof(y1, ymn, invy, NBY);

    float ld = FINF; int lj = 0x7fffffff;
    float b15d = FINF; int b15j = 0x7fffffff;
    bool inited = false;
    const float eps = 1e-4f;

    auto scan = [&](int from, int to) {
        int base = from;
        if (!inited && from < to) {
            int t = from + lane;
            float d; int jj;
            if (t < to) {
                float4 q = __ldg(&pk[t]);
                float s2 = sumsq_ref(q.x, q.y, q.z);
                float dot = __fmaf_rn(z1, q.z,
                            __fmaf_rn(y1, q.y,
                            __fmul_rn(x1, q.x)));
                d = __fmaf_rn(-2.0f, dot, __fadd_rn(s1, s2));
                jj = __float_as_int(q.w);
            } else { d = FINF; jj = 0x7fffffff; }
#pragma unroll
            for (int k = 2; k <= 32; k <<= 1) {
#pragma unroll
                for (int j = k >> 1; j > 0; j >>= 1) {
                    float od = __shfl_xor_sync(FULLM, d, j);
                    int   oj = __shfl_xor_sync(FULLM, jj, j);
                    bool up = ((lane & k) == 0);
                    bool want_min = (((lane & j) == 0) == up);
                    bool mine_lt = LEX_LT(d, jj, od, oj);
                    bool take = (mine_lt != want_min);
                    d = take ? od : d;
                    jj = take ? oj : jj;
                }
            }
            ld = d; lj = jj;
            b15d = __shfl_sync(FULLM, ld, 15);
            b15j = __shfl_sync(FULLM, lj, 15);
            inited = true;
            base = from + 32;
        }
        for (; base < to; base += 32) {
            int t = base + lane;
            float d; int jj;
            if (t < to) {
                float4 q = __ldg(&pk[t]);
                float s2 = sumsq_ref(q.x, q.y, q.z);
                float dot = __fmaf_rn(z1, q.z,
                            __fmaf_rn(y1, q.y,
                            __fmul_rn(x1, q.x)));
                d = __fmaf_rn(-2.0f, dot, __fadd_rn(s1, s2));
                jj = __float_as_int(q.w);
            } else { d = FINF; jj = 0x7fffffff; }
            bool acc = LEX_LT(d, jj, b15d, b15j);
            unsigned am = __ballot_sync(FULLM, acc);
            while (am) {
                int src = __ffs(am) - 1;
                am &= am - 1;
                float cd = __shfl_sync(FULLM, d, src);
                int   cj = __shfl_sync(FULLM, jj, src);
                float pd = __shfl_up_sync(FULLM, ld, 1);
                int   pj = __shfl_up_sync(FULLM, lj, 1);
                if (LEX_LT(cd, cj, ld, lj)) {
                    bool here = (lane == 0) || LEX_LT(pd, pj, cd, cj);
                    ld = here ? cd : pd;
                    lj = here ? cj : pj;
                }
            }
            b15d = __shfl_sync(FULLM, ld, 15);
            b15j = __shfl_sync(FULLM, lj, 15);
        }
    };

    // y-window [yl, yr] for half-width h around y1 (float-clamped: h may be inf).
    auto ybounds = [&](float h, int& yl, int& yr) {
        float fl = (y1 - h - ymn) * invy;
        float fr = (y1 + h - ymn) * invy;
        yl = (int)fminf(fmaxf(fl, 0.0f), (float)(NBY - 1));
        yr = (int)fminf(fmaxf(fr, 0.0f), (float)(NBY - 1));
    };

    // Bootstrap: own row, by +/- BW.
    int rowb = bz * NBY;
    int ylo0 = max(by - BW, 0), yhi0 = min(by + BW, NBY - 1);
    scan(__ldg(&bs[rowb + ylo0]), __ldg(&bs[rowb + yhi0 + 1]));

    // Own-row remainder (disjoint from bootstrap; stale tau => superset, exact).
    {
        float tau = b15d;
        float h = sqrtf(fmaxf(tau + eps, 0.0f));
        int yl, yr; ybounds(h, yl, yr);
        if (yl < ylo0) scan(__ldg(&bs[rowb + yl]), __ldg(&bs[rowb + ylo0]));
        if (yr > yhi0) scan(__ldg(&bs[rowb + yhi0 + 1]), __ldg(&bs[rowb + yr + 1]));
    }

    // Rows outward with exact per-direction stop.
    int up = bz + 1, dn = bz - 1;
    bool uo = true, dno = true;
    while (uo || dno) {
        if (uo) {
            if (up >= NBZ) uo = false;
            else {
                float dz = fmaxf(zmn + (float)up * wz - z1, 0.0f);
                float tau = b15d;
                if (dz * dz > tau + eps) uo = false;
                else {
                    float h = sqrtf(fmaxf(tau + eps - dz * dz, 0.0f));
                    int yl, yr; ybounds(h, yl, yr);
                    int rb = up * NBY;
                    scan(__ldg(&bs[rb + yl]), __ldg(&bs[rb + yr + 1]));
                    up++;
                }
            }
        }
        if (dno) {
            if (dn < 0) dno = false;
            else {
                float dz = fmaxf(z1 - (zmn + (float)(dn + 1) * wz), 0.0f);
                float tau = b15d;
                if (dz * dz > tau + eps) dno = false;
                else {
                    float h = sqrtf(fmaxf(tau + eps - dz * dz, 0.0f));
                    int yl, yr; ybounds(h, yl, yr);
                    int rb = dn * NBY;
                    scan(__ldg(&bs[rb + yl]), __ldg(&bs[rb + yr + 1]));
                    dn--;
                }
            }
        }
    }

    if (lane < KNN_K) {
        long long o = ((long long)n * P1 + i) * KNN_K;
        out[o + lane] = (float)lj;
        out[NPK + o + lane] = ld;
    }
}

extern "C" void kernel_launch(void* const* d_in, const int* in_sizes, int n_in,
                              void* d_out, int out_size) {
    const float* pts[2] = {0, 0};
    const int* lens[2] = {0, 0};
    int lsz[2] = {0, 0};
    int psz[2] = {0, 0};
    int npts = 0, nlen = 0;
    for (int i = 0; i < n_in; i++) {
        if (in_sizes[i] <= 1024) {
            if (nlen < 2) { lens[nlen] = (const int*)d_in[i]; lsz[nlen] = in_sizes[i]; nlen++; }
        } else {
            if (npts < 2) { pts[npts] = (const float*)d_in[i]; psz[npts] = in_sizes[i]; npts++; }
        }
    }
    const float* p1 = pts[0];
    const float* p2 = pts[1];
    const int* l1 = lens[0];
    const int* l2 = lens[1];

    int Nn = lsz[0];
    int P1 = psz[0] / (3 * Nn);
    int P2 = psz[1] / (3 * Nn);
    long long NPK = (long long)out_size / 2;   // first half idx, second half dists

    setup_kernel<<<Nn, 256>>>(p1, p2, l1, l2, P1, P2);

    int P = (P1 > P2) ? P1 : P2;
    scatter_kernel<<<(Nn * P + 255) / 256, 256>>>(p1, p2, l1, l2, Nn, P1, P2);

    zero_kernel<<<512, 256>>>((float*)d_out, (long long)out_size);

    long long threads = (long long)Nn * P1 * 32;
    int blocks = (int)((threads + 255) / 256);
    knn_kernel<<<blocks, 256>>>(p1, l1, (float*)d_out, Nn, P1, P2, NPK);
}

// round 11
// speedup vs baseline: 17.5379x; 1.0338x over previous
#include <cuda_runtime.h>

#define KNN_K 16
#define NBZ   64
#define NBY   64
#define NBB   (NBZ * NBY)
#define C0    64       // bootstrap candidate-count target
#define MAXN  8
#define MAXP  8192
#define FULLM 0xffffffffu
#define FINF  __int_as_float(0x7f800000)

// Static scratch (allocations are forbidden).
__device__ float4 g_pack[MAXN * MAXP];      // bin-sorted targets (x,y,z,idx-bits)
__device__ int    g_qidx[MAXN * MAXP];      // bin-sorted query original index
__device__ int    g_bstart[MAXN * (NBB + 1)];
__device__ int    g_cnt[MAXN * NBB];
__device__ int    g_qcnt[MAXN * NBB];
__device__ float  g_zmin[MAXN], g_invz[MAXN], g_wz[MAXN];
__device__ float  g_ymin[MAXN], g_invy[MAXN];

// ||p||^2 with reference rounding: rn(rn(x*x + y*y) + z*z), products rounded.
__device__ __forceinline__ float sumsq_ref(float x, float y, float z) {
    return __fadd_rn(__fadd_rn(__fmul_rn(x, x), __fmul_rn(y, y)),
                     __fmul_rn(z, z));
}

__device__ __forceinline__ int binof(float v, float vmin, float inv, int nb) {
    int b = (int)((v - vmin) * inv);
    return min(nb - 1, max(0, b));
}

__global__ void setup_kernel(const float* __restrict__ p1,
                             const float* __restrict__ p2,
                             const int* __restrict__ len1,
                             const int* __restrict__ len2,
                             int P1, int P2) {
    int n = blockIdx.x, tid = threadIdx.x;   // 256 threads
    int L1 = len1[n], L2 = len2[n];
    __shared__ int hist[NBB];
    __shared__ int qh[NBB];
    __shared__ float sred[256];
    __shared__ int part[256];

    float zmn = 1e30f, zmx = -1e30f, ymn = 1e30f, ymx = -1e30f;
    for (int j = tid; j < L2; j += 256) {
        const float* p = p2 + ((size_t)n * P2 + j) * 3;
        float y = p[1], z = p[2];
        zmn = fminf(zmn, z); zmx = fmaxf(zmx, z);
        ymn = fminf(ymn, y); ymx = fmaxf(ymx, y);
    }
#define REDUCE(var, op)                                                        \
    sred[tid] = var; __syncthreads();                                          \
    for (int s = 128; s > 0; s >>= 1) {                                        \
        if (tid < s) sred[tid] = op(sred[tid], sred[tid + s]);                 \
        __syncthreads();                                                       \
    }                                                                          \
    var = sred[0]; __syncthreads();
    REDUCE(zmn, fminf) REDUCE(zmx, fmaxf) REDUCE(ymn, fminf) REDUCE(ymx, fmaxf)
#undef REDUCE

    float rz = fmaxf(zmx - zmn, 1e-20f);
    float ry = fmaxf(ymx - ymn, 1e-20f);
    if (tid == 0) {
        g_zmin[n] = zmn; g_invz[n] = (float)NBZ / rz; g_wz[n] = rz / NBZ;
        g_ymin[n] = ymn; g_invy[n] = (float)NBY / ry;
    }
    float invz = (float)NBZ / rz, invy = (float)NBY / ry;

    for (int b = tid; b < NBB; b += 256) { hist[b] = 0; qh[b] = 0; }
    __syncthreads();
    for (int j = tid; j < L2; j += 256) {
        const float* p = p2 + ((size_t)n * P2 + j) * 3;
        int b = binof(p[2], zmn, invz, NBZ) * NBY + binof(p[1], ymn, invy, NBY);
        atomicAdd(&hist[b], 1);
    }
    for (int j = tid; j < L1; j += 256) {
        const float* p = p1 + ((size_t)n * P1 + j) * 3;
        int b = binof(p[2], zmn, invz, NBZ) * NBY + binof(p[1], ymn, invy, NBY);
        atomicAdd(&qh[b], 1);
    }
    __syncthreads();

    // Exclusive scan of hist -> g_bstart, g_cnt. NBB/256 = 16 bins per thread.
    {
        int base = tid * (NBB / 256);
        int s = 0;
        for (int k = 0; k < NBB / 256; k++) s += hist[base + k];
        part[tid] = s; __syncthreads();
        if (tid == 0) {
            int run = 0;
            for (int t = 0; t < 256; t++) { int v = part[t]; part[t] = run; run += v; }
        }
        __syncthreads();
        int run = part[tid];
        for (int k = 0; k < NBB / 256; k++) {
            int b = base + k;
            g_bstart[n * (NBB + 1) + b] = run;
            g_cnt[n * NBB + b] = run;
            run += hist[b];
        }
        if (tid == 255) g_bstart[n * (NBB + 1) + NBB] = run;
        __syncthreads();
    }
    // Exclusive scan of qh -> g_qcnt.
    {
        int base = tid * (NBB / 256);
        int s = 0;
        for (int k = 0; k < NBB / 256; k++) s += qh[base + k];
        part[tid] = s; __syncthreads();
        if (tid == 0) {
            int run = 0;
            for (int t = 0; t < 256; t++) { int v = part[t]; part[t] = run; run += v; }
        }
        __syncthreads();
        int run = part[tid];
        for (int k = 0; k < NBB / 256; k++) {
            int b = base + k;
            g_qcnt[n * NBB + b] = run;
            run += qh[b];
        }
    }
}

__global__ void scatter_kernel(const float* __restrict__ p1,
                               const float* __restrict__ p2,
                               const int* __restrict__ len1,
                               const int* __restrict__ len2,
                               int Nn, int P1, int P2) {
    int t = blockIdx.x * blockDim.x + threadIdx.x;
    int P = max(P1, P2);
    if (t >= Nn * P) return;
    int n = t / P;
    int j = t - n * P;
    float zmn = g_zmin[n], invz = g_invz[n];
    float ymn = g_ymin[n], invy = g_invy[n];
    if (j < P2 && j < len2[n]) {
        const float* p = p2 + ((size_t)n * P2 + j) * 3;
        float x = p[0], y = p[1], z = p[2];
        int b = binof(z, zmn, invz, NBZ) * NBY + binof(y, ymn, invy, NBY);
        int pos = atomicAdd(&g_cnt[n * NBB + b], 1);
        g_pack[n * MAXP + pos] = make_float4(x, y, z, __int_as_float(j));
    }
    if (j < P1 && j < len1[n]) {
        const float* p = p1 + ((size_t)n * P1 + j) * 3;
        int b = binof(p[2], zmn, invz, NBZ) * NBY + binof(p[1], ymn, invy, NBY);
        int pos = atomicAdd(&g_qcnt[n * NBB + b], 1);
        g_qidx[n * MAXP + pos] = j;
    }
}

__global__ void zero_kernel(float* __restrict__ out, long long total) {
    long long t = (long long)blockIdx.x * blockDim.x + threadIdx.x;
    long long stride = (long long)gridDim.x * blockDim.x;
    for (; t < total; t += stride) out[t] = 0.0f;
}

#define LEX_LT(da, ia, db, ib) (((da) < (db)) || (((da) == (db)) && ((ia) < (ib))))

// One warp per query; warp-distributed sorted top list (lane k = k-th best,
// lex on (d, idx); lanes 16..31 sorted overflow).
__global__ __launch_bounds__(256) void knn_kernel(
    const float* __restrict__ p1,
    const int* __restrict__ len1,
    float* __restrict__ out,
    int Nn, int P1, int P2, long long NPK) {

    int gw = (blockIdx.x * blockDim.x + threadIdx.x) >> 5;
    int lane = threadIdx.x & 31;
    if (gw >= Nn * P1) return;
    int n = gw / P1;
    int qs = gw - n * P1;
    int L1 = __ldg(&len1[n]);
    if (qs >= L1) return;                                    // zeros pre-written

    int i = __ldg(&g_qidx[n * MAXP + qs]);
    const float* p = p1 + ((size_t)n * P1 + i) * 3;
    float x1 = __ldg(&p[0]), y1 = __ldg(&p[1]), z1 = __ldg(&p[2]);
    float s1 = sumsq_ref(x1, y1, z1);

    float zmn = g_zmin[n], invz = g_invz[n], wz = g_wz[n];
    float ymn = g_ymin[n], invy = g_invy[n];
    const float4* pk = g_pack + (size_t)n * MAXP;
    const int* bs = g_bstart + n * (NBB + 1);

    int bz = binof(z1, zmn, invz, NBZ);
    int by = binof(y1, ymn, invy, NBY);

    float ld = FINF; int lj = 0x7fffffff;
    float b15d = FINF; int b15j = 0x7fffffff;
    bool inited = false;
    const float eps = 1e-4f;

    auto scan = [&](int from, int to) {
        int base = from;
        if (!inited && from < to) {
            int t = from + lane;
            float d; int jj;
            if (t < to) {
                float4 q = __ldg(&pk[t]);
                float s2 = sumsq_ref(q.x, q.y, q.z);
                float dot = __fmaf_rn(z1, q.z,
                            __fmaf_rn(y1, q.y,
                            __fmul_rn(x1, q.x)));
                d = __fmaf_rn(-2.0f, dot, __fadd_rn(s1, s2));
                jj = __float_as_int(q.w);
            } else { d = FINF; jj = 0x7fffffff; }
#pragma unroll
            for (int k = 2; k <= 32; k <<= 1) {
#pragma unroll
                for (int j = k >> 1; j > 0; j >>= 1) {
                    float od = __shfl_xor_sync(FULLM, d, j);
                    int   oj = __shfl_xor_sync(FULLM, jj, j);
                    bool up = ((lane & k) == 0);
                    bool want_min = (((lane & j) == 0) == up);
                    bool mine_lt = LEX_LT(d, jj, od, oj);
                    bool take = (mine_lt != want_min);
                    d = take ? od : d;
                    jj = take ? oj : jj;
                }
            }
            ld = d; lj = jj;
            b15d = __shfl_sync(FULLM, ld, 15);
            b15j = __shfl_sync(FULLM, lj, 15);
            inited = true;
            base = from + 32;
        }
        for (; base < to; base += 32) {
            int t = base + lane;
            float d; int jj;
            if (t < to) {
                float4 q = __ldg(&pk[t]);
                float s2 = sumsq_ref(q.x, q.y, q.z);
                float dot = __fmaf_rn(z1, q.z,
                            __fmaf_rn(y1, q.y,
                            __fmul_rn(x1, q.x)));
                d = __fmaf_rn(-2.0f, dot, __fadd_rn(s1, s2));
                jj = __float_as_int(q.w);
            } else { d = FINF; jj = 0x7fffffff; }
            bool acc = LEX_LT(d, jj, b15d, b15j);
            unsigned am = __ballot_sync(FULLM, acc);
            while (am) {
                int src = __ffs(am) - 1;
                am &= am - 1;
                float cd = __shfl_sync(FULLM, d, src);
                int   cj = __shfl_sync(FULLM, jj, src);
                float pd = __shfl_up_sync(FULLM, ld, 1);
                int   pj = __shfl_up_sync(FULLM, lj, 1);
                if (LEX_LT(cd, cj, ld, lj)) {
                    bool here = (lane == 0) || LEX_LT(pd, pj, cd, cj);
                    ld = here ? cd : pd;
                    lj = here ? cj : pj;
                }
            }
            b15d = __shfl_sync(FULLM, ld, 15);
            b15j = __shfl_sync(FULLM, lj, 15);
        }
    };

    // y-window [yl, yr] for half-width h around y1 (float-clamped: h may be inf).
    auto ybounds = [&](float h, int& yl, int& yr) {
        float fl = (y1 - h - ymn) * invy;
        float fr = (y1 + h - ymn) * invy;
        yl = (int)fminf(fmaxf(fl, 0.0f), (float)(NBY - 1));
        yr = (int)fminf(fmaxf(fr, 0.0f), (float)(NBY - 1));
    };

    // Bootstrap: expand around the query's own (z,y) bin until >= C0 candidates.
    int rowb = bz * NBY;
    int ylo0 = by, yhi0 = by;
    {
        int from = __ldg(&bs[rowb + ylo0]), to = __ldg(&bs[rowb + yhi0 + 1]);
        bool side = true;
        while (to - from < C0) {
            bool canR = (yhi0 < NBY - 1), canL = (ylo0 > 0);
            if (!canR && !canL) break;
            if ((side && canR) || !canL) { yhi0++; to = __ldg(&bs[rowb + yhi0 + 1]); }
            else { ylo0--; from = __ldg(&bs[rowb + ylo0]); }
            side = !side;
        }
        scan(from, to);
    }

    // Own-row remainder (disjoint from bootstrap; stale tau => superset, exact).
    {
        float tau = b15d;
        float h = sqrtf(fmaxf(tau + eps, 0.0f));
        int yl, yr; ybounds(h, yl, yr);
        if (yl < ylo0) scan(__ldg(&bs[rowb + yl]), __ldg(&bs[rowb + ylo0]));
        if (yr > yhi0) scan(__ldg(&bs[rowb + yhi0 + 1]), __ldg(&bs[rowb + yr + 1]));
    }

    // Rows outward with exact per-direction stop.
    int up = bz + 1, dn = bz - 1;
    bool uo = true, dno = true;
    while (uo || dno) {
        if (uo) {
            if (up >= NBZ) uo = false;
            else {
                float dz = fmaxf(zmn + (float)up * wz - z1, 0.0f);
                float tau = b15d;
                if (dz * dz > tau + eps) uo = false;
                else {
                    float h = sqrtf(fmaxf(tau + eps - dz * dz, 0.0f));
                    int yl, yr; ybounds(h, yl, yr);
                    int rb = up * NBY;
                    scan(__ldg(&bs[rb + yl]), __ldg(&bs[rb + yr + 1]));
                    up++;
                }
            }
        }
        if (dno) {
            if (dn < 0) dno = false;
            else {
                float dz = fmaxf(z1 - (zmn + (float)(dn + 1) * wz), 0.0f);
                float tau = b15d;
                if (dz * dz > tau + eps) dno = false;
                else {
                    float h = sqrtf(fmaxf(tau + eps - dz * dz, 0.0f));
                    int yl, yr; ybounds(h, yl, yr);
                    int rb = dn * NBY;
                    scan(__ldg(&bs[rb + yl]), __ldg(&bs[rb + yr + 1]));
                    dn--;
                }
            }
        }
    }

    if (lane < KNN_K) {
        long long o = ((long long)n * P1 + i) * KNN_K;
        out[o + lane] = (float)lj;
        out[NPK + o + lane] = ld;
    }
}

extern "C" void kernel_launch(void* const* d_in, const int* in_sizes, int n_in,
                              void* d_out, int out_size) {
    const float* pts[2] = {0, 0};
    const int* lens[2] = {0, 0};
    int lsz[2] = {0, 0};
    int psz[2] = {0, 0};
    int npts = 0, nlen = 0;
    for (int i = 0; i < n_in; i++) {
        if (in_sizes[i] <= 1024) {
            if (nlen < 2) { lens[nlen] = (const int*)d_in[i]; lsz[nlen] = in_sizes[i]; nlen++; }
        } else {
            if (npts < 2) { pts[npts] = (const float*)d_in[i]; psz[npts] = in_sizes[i]; npts++; }
        }
    }
    const float* p1 = pts[0];
    const float* p2 = pts[1];
    const int* l1 = lens[0];
    const int* l2 = lens[1];

    int Nn = lsz[0];
    int P1 = psz[0] / (3 * Nn);
    int P2 = psz[1] / (3 * Nn);
    long long NPK = (long long)out_size / 2;   // first half idx, second half dists

    setup_kernel<<<Nn, 256>>>(p1, p2, l1, l2, P1, P2);

    int P = (P1 > P2) ? P1 : P2;
    scatter_kernel<<<(Nn * P + 255) / 256, 256>>>(p1, p2, l1, l2, Nn, P1, P2);

    zero_kernel<<<512, 256>>>((float*)d_out, (long long)out_size);

    long long threads = (long long)Nn * P1 * 32;
    int blocks = (int)((threads + 255) / 256);
    knn_kernel<<<blocks, 256>>>(p1, l1, (float*)d_out, Nn, P1, P2, NPK);
}

// round 12
// speedup vs baseline: 17.5893x; 1.0029x over previous
#include <cuda_runtime.h>

#define KNN_K 16
#define NBZ   64
#define NBY   64
#define NBB   (NBZ * NBY)
#define C0    64       // bootstrap candidate-count target
#define MAXN  8
#define MAXP  8192
#define FULLM 0xffffffffu
#define FINF  __int_as_float(0x7f800000)

// Static scratch (allocations are forbidden).
__device__ float4 g_pack[MAXN * MAXP];      // bin-sorted targets (x,y,z,idx-bits)
__device__ float  g_s2[MAXN * MAXP];        // bin-sorted ||p2||^2 (reference rounding)
__device__ int    g_qidx[MAXN * MAXP];      // bin-sorted query original index
__device__ int    g_bstart[MAXN * (NBB + 1)];
__device__ int    g_cnt[MAXN * NBB];
__device__ int    g_qcnt[MAXN * NBB];
__device__ float  g_zmin[MAXN], g_invz[MAXN], g_wz[MAXN];
__device__ float  g_ymin[MAXN], g_invy[MAXN];

// ||p||^2 with reference rounding: rn(rn(x*x + y*y) + z*z), products rounded.
__device__ __forceinline__ float sumsq_ref(float x, float y, float z) {
    return __fadd_rn(__fadd_rn(__fmul_rn(x, x), __fmul_rn(y, y)),
                     __fmul_rn(z, z));
}

__device__ __forceinline__ int binof(float v, float vmin, float inv, int nb) {
    int b = (int)((v - vmin) * inv);
    return min(nb - 1, max(0, b));
}

__global__ void setup_kernel(const float* __restrict__ p1,
                             const float* __restrict__ p2,
                             const int* __restrict__ len1,
                             const int* __restrict__ len2,
                             int P1, int P2) {
    int n = blockIdx.x, tid = threadIdx.x;   // 256 threads
    int L1 = len1[n], L2 = len2[n];
    __shared__ int hist[NBB];
    __shared__ int qh[NBB];
    __shared__ float sred[256];
    __shared__ int part[256];

    float zmn = 1e30f, zmx = -1e30f, ymn = 1e30f, ymx = -1e30f;
    for (int j = tid; j < L2; j += 256) {
        const float* p = p2 + ((size_t)n * P2 + j) * 3;
        float y = p[1], z = p[2];
        zmn = fminf(zmn, z); zmx = fmaxf(zmx, z);
        ymn = fminf(ymn, y); ymx = fmaxf(ymx, y);
    }
#define REDUCE(var, op)                                                        \
    sred[tid] = var; __syncthreads();                                          \
    for (int s = 128; s > 0; s >>= 1) {                                        \
        if (tid < s) sred[tid] = op(sred[tid], sred[tid + s]);                 \
        __syncthreads();                                                       \
    }                                                                          \
    var = sred[0]; __syncthreads();
    REDUCE(zmn, fminf) REDUCE(zmx, fmaxf) REDUCE(ymn, fminf) REDUCE(ymx, fmaxf)
#undef REDUCE

    float rz = fmaxf(zmx - zmn, 1e-20f);
    float ry = fmaxf(ymx - ymn, 1e-20f);
    if (tid == 0) {
        g_zmin[n] = zmn; g_invz[n] = (float)NBZ / rz; g_wz[n] = rz / NBZ;
        g_ymin[n] = ymn; g_invy[n] = (float)NBY / ry;
    }
    float invz = (float)NBZ / rz, invy = (float)NBY / ry;

    for (int b = tid; b < NBB; b += 256) { hist[b] = 0; qh[b] = 0; }
    __syncthreads();
    for (int j = tid; j < L2; j += 256) {
        const float* p = p2 + ((size_t)n * P2 + j) * 3;
        int b = binof(p[2], zmn, invz, NBZ) * NBY + binof(p[1], ymn, invy, NBY);
        atomicAdd(&hist[b], 1);
    }
    for (int j = tid; j < L1; j += 256) {
        const float* p = p1 + ((size_t)n * P1 + j) * 3;
        int b = binof(p[2], zmn, invz, NBZ) * NBY + binof(p[1], ymn, invy, NBY);
        atomicAdd(&qh[b], 1);
    }
    __syncthreads();

    // Exclusive scan of hist -> g_bstart, g_cnt. NBB/256 = 16 bins per thread.
    {
        int base = tid * (NBB / 256);
        int s = 0;
        for (int k = 0; k < NBB / 256; k++) s += hist[base + k];
        part[tid] = s; __syncthreads();
        if (tid == 0) {
            int run = 0;
            for (int t = 0; t < 256; t++) { int v = part[t]; part[t] = run; run += v; }
        }
        __syncthreads();
        int run = part[tid];
        for (int k = 0; k < NBB / 256; k++) {
            int b = base + k;
            g_bstart[n * (NBB + 1) + b] = run;
            g_cnt[n * NBB + b] = run;
            run += hist[b];
        }
        if (tid == 255) g_bstart[n * (NBB + 1) + NBB] = run;
        __syncthreads();
    }
    // Exclusive scan of qh -> g_qcnt.
    {
        int base = tid * (NBB / 256);
        int s = 0;
        for (int k = 0; k < NBB / 256; k++) s += qh[base + k];
        part[tid] = s; __syncthreads();
        if (tid == 0) {
            int run = 0;
            for (int t = 0; t < 256; t++) { int v = part[t]; part[t] = run; run += v; }
        }
        __syncthreads();
        int run = part[tid];
        for (int k = 0; k < NBB / 256; k++) {
            int b = base + k;
            g_qcnt[n * NBB + b] = run;
            run += qh[b];
        }
    }
}

__global__ void scatter_kernel(const float* __restrict__ p1,
                               const float* __restrict__ p2,
                               const int* __restrict__ len1,
                               const int* __restrict__ len2,
                               int Nn, int P1, int P2) {
    int t = blockIdx.x * blockDim.x + threadIdx.x;
    int P = max(P1, P2);
    if (t >= Nn * P) return;
    int n = t / P;
    int j = t - n * P;
    float zmn = g_zmin[n], invz = g_invz[n];
    float ymn = g_ymin[n], invy = g_invy[n];
    if (j < P2 && j < len2[n]) {
        const float* p = p2 + ((size_t)n * P2 + j) * 3;
        float x = p[0], y = p[1], z = p[2];
        int b = binof(z, zmn, invz, NBZ) * NBY + binof(y, ymn, invy, NBY);
        int pos = atomicAdd(&g_cnt[n * NBB + b], 1);
        g_pack[n * MAXP + pos] = make_float4(x, y, z, __int_as_float(j));
        g_s2[n * MAXP + pos] = sumsq_ref(x, y, z);
    }
    if (j < P1 && j < len1[n]) {
        const float* p = p1 + ((size_t)n * P1 + j) * 3;
        int b = binof(p[2], zmn, invz, NBZ) * NBY + binof(p[1], ymn, invy, NBY);
        int pos = atomicAdd(&g_qcnt[n * NBB + b], 1);
        g_qidx[n * MAXP + pos] = j;
    }
}

#define LEX_LT(da, ia, db, ib) (((da) < (db)) || (((da) == (db)) && ((ia) < (ib))))

// Warp bitonic sort-32 (ascending lex) of (d, jj) across lanes.
#define BSORT32(d, jj)                                                         \
    _Pragma("unroll")                                                          \
    for (int k = 2; k <= 32; k <<= 1) {                                        \
        _Pragma("unroll")                                                      \
        for (int j = k >> 1; j > 0; j >>= 1) {                                 \
            float od = __shfl_xor_sync(FULLM, d, j);                           \
            int   oj = __shfl_xor_sync(FULLM, jj, j);                          \
            bool up = ((lane & k) == 0);                                       \
            bool want_min = (((lane & j) == 0) == up);                         \
            bool mine_lt = LEX_LT(d, jj, od, oj);                              \
            bool take = (mine_lt != want_min);                                 \
            d = take ? od : d;                                                 \
            jj = take ? oj : jj;                                               \
        }                                                                      \
    }

// One warp per query; warp-distributed sorted top list (lane k = k-th best,
// lex on (d, idx); lanes 16..31 sorted overflow).
__global__ __launch_bounds__(256) void knn_kernel(
    const float* __restrict__ p1,
    const int* __restrict__ len1,
    float* __restrict__ out,
    int Nn, int P1, int P2, long long NPK) {

    int gw = (blockIdx.x * blockDim.x + threadIdx.x) >> 5;
    int lane = threadIdx.x & 31;
    if (gw >= Nn * P1) return;
    int n = gw / P1;
    int qs = gw - n * P1;
    int L1 = __ldg(&len1[n]);
    if (qs >= L1) {
        // Padded slots [L1,P1) biject onto padded rows i=qs: write zeros here.
        if (lane < KNN_K) {
            long long o = ((long long)n * P1 + qs) * KNN_K;
            out[o + lane] = 0.0f;
            out[NPK + o + lane] = 0.0f;
        }
        return;
    }

    int i = __ldg(&g_qidx[n * MAXP + qs]);
    const float* p = p1 + ((size_t)n * P1 + i) * 3;
    float x1 = __ldg(&p[0]), y1 = __ldg(&p[1]), z1 = __ldg(&p[2]);
    float s1 = sumsq_ref(x1, y1, z1);

    float zmn = g_zmin[n], invz = g_invz[n], wz = g_wz[n];
    float ymn = g_ymin[n], invy = g_invy[n];
    const float4* pk = g_pack + (size_t)n * MAXP;
    const float* ps2 = g_s2 + (size_t)n * MAXP;
    const int* bs = g_bstart + n * (NBB + 1);

    int bz = binof(z1, zmn, invz, NBZ);
    int by = binof(y1, ymn, invy, NBY);

    float ld = FINF; int lj = 0x7fffffff;
    float b15d = FINF; int b15j = 0x7fffffff;
    bool inited = false;
    const float eps = 1e-4f;

    auto scan = [&](int from, int to) {
        int base = from;
        if (!inited && from < to) {
            int t = from + lane;
            float d; int jj;
            if (t < to) {
                float4 q = __ldg(&pk[t]);
                float s2 = __ldg(&ps2[t]);
                float dot = __fmaf_rn(z1, q.z,
                            __fmaf_rn(y1, q.y,
                            __fmul_rn(x1, q.x)));
                d = __fmaf_rn(-2.0f, dot, __fadd_rn(s1, s2));
                jj = __float_as_int(q.w);
            } else { d = FINF; jj = 0x7fffffff; }
            BSORT32(d, jj)
            ld = d; lj = jj;
            b15d = __shfl_sync(FULLM, ld, 15);
            b15j = __shfl_sync(FULLM, lj, 15);
            inited = true;
            base = from + 32;
        }
        for (; base < to; base += 32) {
            int t = base + lane;
            float d; int jj;
            if (t < to) {
                float4 q = __ldg(&pk[t]);
                float s2 = __ldg(&ps2[t]);
                float dot = __fmaf_rn(z1, q.z,
                            __fmaf_rn(y1, q.y,
                            __fmul_rn(x1, q.x)));
                d = __fmaf_rn(-2.0f, dot, __fadd_rn(s1, s2));
                jj = __float_as_int(q.w);
            } else { d = FINF; jj = 0x7fffffff; }
            bool acc = LEX_LT(d, jj, b15d, b15j);
            unsigned am = __ballot_sync(FULLM, acc);
            if (!am) continue;
            if (__popc(am) >= 10) {
                // Bulk path: sort batch, bitonic-merge with list (keep lowest 32).
                // Non-accepted lanes are lex >= b15: land in overflow, harmless.
                BSORT32(d, jj)
                float rd = __shfl_sync(FULLM, d, 31 - lane);
                int   rj = __shfl_sync(FULLM, jj, 31 - lane);
                bool keep = LEX_LT(ld, lj, rd, rj);
                float md = keep ? ld : rd;
                int   mj = keep ? lj : rj;
#pragma unroll
                for (int j = 16; j > 0; j >>= 1) {
                    float od = __shfl_xor_sync(FULLM, md, j);
                    int   oj = __shfl_xor_sync(FULLM, mj, j);
                    bool lower = ((lane & j) == 0);
                    bool mine_lt = LEX_LT(md, mj, od, oj);
                    bool take = (mine_lt != lower);
                    md = take ? od : md;
                    mj = take ? oj : mj;
                }
                ld = md; lj = mj;
            } else {
                while (am) {
                    int src = __ffs(am) - 1;
                    am &= am - 1;
                    float cd = __shfl_sync(FULLM, d, src);
                    int   cj = __shfl_sync(FULLM, jj, src);
                    float pd = __shfl_up_sync(FULLM, ld, 1);
                    int   pj = __shfl_up_sync(FULLM, lj, 1);
                    if (LEX_LT(cd, cj, ld, lj)) {
                        bool here = (lane == 0) || LEX_LT(pd, pj, cd, cj);
                        ld = here ? cd : pd;
                        lj = here ? cj : pj;
                    }
                }
            }
            b15d = __shfl_sync(FULLM, ld, 15);
            b15j = __shfl_sync(FULLM, lj, 15);
        }
    };

    // y-window [yl, yr] for half-width h around y1 (float-clamped: h may be inf).
    auto ybounds = [&](float h, int& yl, int& yr) {
        float fl = (y1 - h - ymn) * invy;
        float fr = (y1 + h - ymn) * invy;
        yl = (int)fminf(fmaxf(fl, 0.0f), (float)(NBY - 1));
        yr = (int)fminf(fmaxf(fr, 0.0f), (float)(NBY - 1));
    };

    // Bootstrap: expand around the query's own (z,y) bin until >= C0 candidates.
    int rowb = bz * NBY;
    int ylo0 = by, yhi0 = by;
    {
        int from = __ldg(&bs[rowb + ylo0]), to = __ldg(&bs[rowb + yhi0 + 1]);
        bool side = true;
        while (to - from < C0) {
            bool canR = (yhi0 < NBY - 1), canL = (ylo0 > 0);
            if (!canR && !canL) break;
            if ((side && canR) || !canL) { yhi0++; to = __ldg(&bs[rowb + yhi0 + 1]); }
            else { ylo0--; from = __ldg(&bs[rowb + ylo0]); }
            side = !side;
        }
        scan(from, to);
    }

    // Own-row remainder (disjoint from bootstrap; stale tau => superset, exact).
    {
        float tau = b15d;
        float h = sqrtf(fmaxf(tau + eps, 0.0f));
        int yl, yr; ybounds(h, yl, yr);
        if (yl < ylo0) scan(__ldg(&bs[rowb + yl]), __ldg(&bs[rowb + ylo0]));
        if (yr > yhi0) scan(__ldg(&bs[rowb + yhi0 + 1]), __ldg(&bs[rowb + yr + 1]));
    }

    // Rows outward with exact per-direction stop.
    int up = bz + 1, dn = bz - 1;
    bool uo = true, dno = true;
    while (uo || dno) {
        if (uo) {
            if (up >= NBZ) uo = false;
            else {
                float dz = fmaxf(zmn + (float)up * wz - z1, 0.0f);
                float tau = b15d;
                if (dz * dz > tau + eps) uo = false;
                else {
                    float h = sqrtf(fmaxf(tau + eps - dz * dz, 0.0f));
                    int yl, yr; ybounds(h, yl, yr);
                    int rb = up * NBY;
                    scan(__ldg(&bs[rb + yl]), __ldg(&bs[rb + yr + 1]));
                    up++;
                }
            }
        }
        if (dno) {
            if (dn < 0) dno = false;
            else {
                float dz = fmaxf(z1 - (zmn + (float)(dn + 1) * wz), 0.0f);
                float tau = b15d;
                if (dz * dz > tau + eps) dno = false;
                else {
                    float h = sqrtf(fmaxf(tau + eps - dz * dz, 0.0f));
                    int yl, yr; ybounds(h, yl, yr);
                    int rb = dn * NBY;
                    scan(__ldg(&bs[rb + yl]), __ldg(&bs[rb + yr + 1]));
                    dn--;
                }
            }
        }
    }

    if (lane < KNN_K) {
        long long o = ((long long)n * P1 + i) * KNN_K;
        out[o + lane] = (float)lj;
        out[NPK + o + lane] = ld;
    }
}

extern "C" void kernel_launch(void* const* d_in, const int* in_sizes, int n_in,
                              void* d_out, int out_size) {
    const float* pts[2] = {0, 0};
    const int* lens[2] = {0, 0};
    int lsz[2] = {0, 0};
    int psz[2] = {0, 0};
    int npts = 0, nlen = 0;
    for (int i = 0; i < n_in; i++) {
        if (in_sizes[i] <= 1024) {
            if (nlen < 2) { lens[nlen] = (const int*)d_in[i]; lsz[nlen] = in_sizes[i]; nlen++; }
        } else {
            if (npts < 2) { pts[npts] = (const float*)d_in[i]; psz[npts] = in_sizes[i]; npts++; }
        }
    }
    const float* p1 = pts[0];
    const float* p2 = pts[1];
    const int* l1 = lens[0];
    const int* l2 = lens[1];

    int Nn = lsz[0];
    int P1 = psz[0] / (3 * Nn);
    int P2 = psz[1] / (3 * Nn);
    long long NPK = (long long)out_size / 2;   // first half idx, second half dists

    setup_kernel<<<Nn, 256>>>(p1, p2, l1, l2, P1, P2);

    int P = (P1 > P2) ? P1 : P2;
    scatter_kernel<<<(Nn * P + 255) / 256, 256>>>(p1, p2, l1, l2, Nn, P1, P2);

    long long threads = (long long)Nn * P1 * 32;
    int blocks = (int)((threads + 255) / 256);
    knn_kernel<<<blocks, 256>>>(p1, l1, (float*)d_out, Nn, P1, P2, NPK);
}

// round 13
// speedup vs baseline: 18.4110x; 1.0467x over previous
#include <cuda_runtime.h>

#define KNN_K 16
#define NBZ   64
#define NBY   64
#define NBB   (NBZ * NBY)
#define C0    64       // bootstrap candidate-count target
#define MAXN  8
#define MAXP  8192
#define FULLM 0xffffffffu
#define FINF  __int_as_float(0x7f800000)

// Fixed bin bounds: correctness holds for ANY bounds (clamped partition);
// these only tune bin quality for ~N(0,1) data.
#define BMIN  (-6.0f)
#define BRNG  (12.0f)
#define WZ    (BRNG / NBZ)
#define INVZ  (NBZ / BRNG)
#define WY    (BRNG / NBY)
#define INVY  (NBY / BRNG)

// Static scratch (allocations are forbidden).
__device__ float4 g_pack[MAXN * MAXP];      // bin-sorted targets (x,y,z,idx-bits)
__device__ float  g_s2[MAXN * MAXP];        // bin-sorted ||p2||^2 (reference rounding)
__device__ int    g_qidx[MAXN * MAXP];      // bin-sorted query original index
__device__ int    g_bstart[MAXN * (NBB + 1)];
__device__ int    g_cnt[MAXN * NBB];        // hist counts -> scatter cursors
__device__ int    g_qcnt[MAXN * NBB];

// ||p||^2 with reference rounding: rn(rn(x*x + y*y) + z*z), products rounded.
__device__ __forceinline__ float sumsq_ref(float x, float y, float z) {
    return __fadd_rn(__fadd_rn(__fmul_rn(x, x), __fmul_rn(y, y)),
                     __fmul_rn(z, z));
}

__device__ __forceinline__ int binz(float z) {
    int b = (int)((z - BMIN) * INVZ);
    return min(NBZ - 1, max(0, b));
}
__device__ __forceinline__ int biny(float y) {
    int b = (int)((y - BMIN) * INVY);
    return min(NBY - 1, max(0, b));
}

__global__ void zero_hist_kernel(int Nn) {
    int t = blockIdx.x * blockDim.x + threadIdx.x;
    if (t < Nn * NBB) { g_cnt[t] = 0; g_qcnt[t] = 0; }
}

__global__ void hist_kernel(const float* __restrict__ p1,
                            const float* __restrict__ p2,
                            const int* __restrict__ len1,
                            const int* __restrict__ len2,
                            int Nn, int P1, int P2) {
    int t = blockIdx.x * blockDim.x + threadIdx.x;
    int P = max(P1, P2);
    if (t >= Nn * P) return;
    int n = t / P;
    int j = t - n * P;
    if (j < P2 && j < __ldg(&len2[n])) {
        const float* p = p2 + ((size_t)n * P2 + j) * 3;
        atomicAdd(&g_cnt[n * NBB + binz(p[2]) * NBY + biny(p[1])], 1);
    }
    if (j < P1 && j < __ldg(&len1[n])) {
        const float* p = p1 + ((size_t)n * P1 + j) * 3;
        atomicAdd(&g_qcnt[n * NBB + binz(p[2]) * NBY + biny(p[1])], 1);
    }
}

// One block per batch: two-level exclusive scan of both histograms.
__global__ void scan_kernel(int Nn) {
    int n = blockIdx.x, tid = threadIdx.x;   // 256 threads
    __shared__ int part[256];
    const int BPT = NBB / 256;               // 16 bins per thread

    // Targets: counts -> g_bstart (starts), g_cnt = cursor starts.
    {
        int base = tid * BPT;
        int cnts[BPT];
        int s = 0;
#pragma unroll
        for (int k = 0; k < BPT; k++) { cnts[k] = g_cnt[n * NBB + base + k]; s += cnts[k]; }
        part[tid] = s; __syncthreads();
        if (tid == 0) {
            int run = 0;
            for (int t = 0; t < 256; t++) { int v = part[t]; part[t] = run; run += v; }
        }
        __syncthreads();
        int run = part[tid];
#pragma unroll
        for (int k = 0; k < BPT; k++) {
            int b = base + k;
            g_bstart[n * (NBB + 1) + b] = run;
            g_cnt[n * NBB + b] = run;
            run += cnts[k];
        }
        if (tid == 255) g_bstart[n * (NBB + 1) + NBB] = run;
        __syncthreads();
    }
    // Queries.
    {
        int base = tid * BPT;
        int cnts[BPT];
        int s = 0;
#pragma unroll
        for (int k = 0; k < BPT; k++) { cnts[k] = g_qcnt[n * NBB + base + k]; s += cnts[k]; }
        part[tid] = s; __syncthreads();
        if (tid == 0) {
            int run = 0;
            for (int t = 0; t < 256; t++) { int v = part[t]; part[t] = run; run += v; }
        }
        __syncthreads();
        int run = part[tid];
#pragma unroll
        for (int k = 0; k < BPT; k++) {
            g_qcnt[n * NBB + base + k] = run;
            run += cnts[k];
        }
    }
}

__global__ void scatter_kernel(const float* __restrict__ p1,
                               const float* __restrict__ p2,
                               const int* __restrict__ len1,
                               const int* __restrict__ len2,
                               int Nn, int P1, int P2) {
    int t = blockIdx.x * blockDim.x + threadIdx.x;
    int P = max(P1, P2);
    if (t >= Nn * P) return;
    int n = t / P;
    int j = t - n * P;
    if (j < P2 && j < __ldg(&len2[n])) {
        const float* p = p2 + ((size_t)n * P2 + j) * 3;
        float x = p[0], y = p[1], z = p[2];
        int b = binz(z) * NBY + biny(y);
        int pos = atomicAdd(&g_cnt[n * NBB + b], 1);
        g_pack[n * MAXP + pos] = make_float4(x, y, z, __int_as_float(j));
        g_s2[n * MAXP + pos] = sumsq_ref(x, y, z);
    }
    if (j < P1 && j < __ldg(&len1[n])) {
        const float* p = p1 + ((size_t)n * P1 + j) * 3;
        int b = binz(p[2]) * NBY + biny(p[1]);
        int pos = atomicAdd(&g_qcnt[n * NBB + b], 1);
        g_qidx[n * MAXP + pos] = j;
    }
}

#define LEX_LT(da, ia, db, ib) (((da) < (db)) || (((da) == (db)) && ((ia) < (ib))))

// Warp bitonic sort-32 (ascending lex) of (d, jj) across lanes.
#define BSORT32(d, jj)                                                         \
    _Pragma("unroll")                                                          \
    for (int k = 2; k <= 32; k <<= 1) {                                        \
        _Pragma("unroll")                                                      \
        for (int j = k >> 1; j > 0; j >>= 1) {                                 \
            float od = __shfl_xor_sync(FULLM, d, j);                           \
            int   oj = __shfl_xor_sync(FULLM, jj, j);                          \
            bool up = ((lane & k) == 0);                                       \
            bool want_min = (((lane & j) == 0) == up);                         \
            bool mine_lt = LEX_LT(d, jj, od, oj);                              \
            bool take = (mine_lt != want_min);                                 \
            d = take ? od : d;                                                 \
            jj = take ? oj : jj;                                               \
        }                                                                      \
    }

// One warp per query; warp-distributed sorted top list (lane k = k-th best,
// lex on (d, idx); lanes 16..31 sorted overflow).
__global__ __launch_bounds__(256) void knn_kernel(
    const float* __restrict__ p1,
    const int* __restrict__ len1,
    float* __restrict__ out,
    int Nn, int P1, int P2, long long NPK) {

    int gw = (blockIdx.x * blockDim.x + threadIdx.x) >> 5;
    int lane = threadIdx.x & 31;
    if (gw >= Nn * P1) return;
    int n = gw / P1;
    int qs = gw - n * P1;
    int L1 = __ldg(&len1[n]);
    if (qs >= L1) {
        // Padded slots [L1,P1) biject onto padded rows i=qs: write zeros here.
        if (lane < KNN_K) {
            long long o = ((long long)n * P1 + qs) * KNN_K;
            out[o + lane] = 0.0f;
            out[NPK + o + lane] = 0.0f;
        }
        return;
    }

    int i = __ldg(&g_qidx[n * MAXP + qs]);
    const float* p = p1 + ((size_t)n * P1 + i) * 3;
    float x1 = __ldg(&p[0]), y1 = __ldg(&p[1]), z1 = __ldg(&p[2]);
    float s1 = sumsq_ref(x1, y1, z1);

    const float4* pk = g_pack + (size_t)n * MAXP;
    const float* ps2 = g_s2 + (size_t)n * MAXP;
    const int* bs = g_bstart + n * (NBB + 1);

    int bz = binz(z1);
    int by = biny(y1);

    float ld = FINF; int lj = 0x7fffffff;
    float b15d = FINF; int b15j = 0x7fffffff;
    bool inited = false;
    const float eps = 1e-4f;

    auto scan = [&](int from, int to) {
        int base = from;
        if (!inited && from < to) {
            int t = from + lane;
            float d; int jj;
            if (t < to) {
                float4 q = __ldg(&pk[t]);
                float s2 = __ldg(&ps2[t]);
                float dot = __fmaf_rn(z1, q.z,
                            __fmaf_rn(y1, q.y,
                            __fmul_rn(x1, q.x)));
                d = __fmaf_rn(-2.0f, dot, __fadd_rn(s1, s2));
                jj = __float_as_int(q.w);
            } else { d = FINF; jj = 0x7fffffff; }
            BSORT32(d, jj)
            ld = d; lj = jj;
            b15d = __shfl_sync(FULLM, ld, 15);
            b15j = __shfl_sync(FULLM, lj, 15);
            inited = true;
            base = from + 32;
        }
        for (; base < to; base += 32) {
            int t = base + lane;
            float d; int jj;
            if (t < to) {
                float4 q = __ldg(&pk[t]);
                float s2 = __ldg(&ps2[t]);
                float dot = __fmaf_rn(z1, q.z,
                            __fmaf_rn(y1, q.y,
                            __fmul_rn(x1, q.x)));
                d = __fmaf_rn(-2.0f, dot, __fadd_rn(s1, s2));
                jj = __float_as_int(q.w);
            } else { d = FINF; jj = 0x7fffffff; }
            bool acc = LEX_LT(d, jj, b15d, b15j);
            unsigned am = __ballot_sync(FULLM, acc);
            if (!am) continue;
            if (__popc(am) >= 10) {
                // Bulk path: sort batch, bitonic-merge with list (keep lowest 32).
                BSORT32(d, jj)
                float rd = __shfl_sync(FULLM, d, 31 - lane);
                int   rj = __shfl_sync(FULLM, jj, 31 - lane);
                bool keep = LEX_LT(ld, lj, rd, rj);
                float md = keep ? ld : rd;
                int   mj = keep ? lj : rj;
#pragma unroll
                for (int j = 16; j > 0; j >>= 1) {
                    float od = __shfl_xor_sync(FULLM, md, j);
                    int   oj = __shfl_xor_sync(FULLM, mj, j);
                    bool lower = ((lane & j) == 0);
                    bool mine_lt = LEX_LT(md, mj, od, oj);
                    bool take = (mine_lt != lower);
                    md = take ? od : md;
                    mj = take ? oj : mj;
                }
                ld = md; lj = mj;
            } else {
                while (am) {
                    int src = __ffs(am) - 1;
                    am &= am - 1;
                    float cd = __shfl_sync(FULLM, d, src);
                    int   cj = __shfl_sync(FULLM, jj, src);
                    float pd = __shfl_up_sync(FULLM, ld, 1);
                    int   pj = __shfl_up_sync(FULLM, lj, 1);
                    if (LEX_LT(cd, cj, ld, lj)) {
                        bool here = (lane == 0) || LEX_LT(pd, pj, cd, cj);
                        ld = here ? cd : pd;
                        lj = here ? cj : pj;
                    }
                }
            }
            b15d = __shfl_sync(FULLM, ld, 15);
            b15j = __shfl_sync(FULLM, lj, 15);
        }
    };

    // y-window [yl, yr] for half-width h around y1 (float-clamped: h may be inf).
    auto ybounds = [&](float h, int& yl, int& yr) {
        float fl = (y1 - h - BMIN) * INVY;
        float fr = (y1 + h - BMIN) * INVY;
        yl = (int)fminf(fmaxf(fl, 0.0f), (float)(NBY - 1));
        yr = (int)fminf(fmaxf(fr, 0.0f), (float)(NBY - 1));
    };

    // Bootstrap: expand around the query's own (z,y) bin until >= C0 candidates.
    int rowb = bz * NBY;
    int ylo0 = by, yhi0 = by;
    {
        int from = __ldg(&bs[rowb + ylo0]), to = __ldg(&bs[rowb + yhi0 + 1]);
        bool side = true;
        while (to - from < C0) {
            bool canR = (yhi0 < NBY - 1), canL = (ylo0 > 0);
            if (!canR && !canL) break;
            if ((side && canR) || !canL) { yhi0++; to = __ldg(&bs[rowb + yhi0 + 1]); }
            else { ylo0--; from = __ldg(&bs[rowb + ylo0]); }
            side = !side;
        }
        scan(from, to);
    }

    // Own-row remainder (disjoint from bootstrap; stale tau => superset, exact).
    {
        float tau = b15d;
        float h = sqrtf(fmaxf(tau + eps, 0.0f));
        int yl, yr; ybounds(h, yl, yr);
        if (yl < ylo0) scan(__ldg(&bs[rowb + yl]), __ldg(&bs[rowb + ylo0]));
        if (yr > yhi0) scan(__ldg(&bs[rowb + yhi0 + 1]), __ldg(&bs[rowb + yr + 1]));
    }

    // Rows outward with exact per-direction stop.
    int up = bz + 1, dn = bz - 1;
    bool uo = true, dno = true;
    while (uo || dno) {
        if (uo) {
            if (up >= NBZ) uo = false;
            else {
                float dz = fmaxf(BMIN + (float)up * WZ - z1, 0.0f);
                float tau = b15d;
                if (dz * dz > tau + eps) uo = false;
                else {
                    float h = sqrtf(fmaxf(tau + eps - dz * dz, 0.0f));
                    int yl, yr; ybounds(h, yl, yr);
                    int rb = up * NBY;
                    scan(__ldg(&bs[rb + yl]), __ldg(&bs[rb + yr + 1]));
                    up++;
                }
            }
        }
        if (dno) {
            if (dn < 0) dno = false;
            else {
                float dz = fmaxf(z1 - (BMIN + (float)(dn + 1) * WZ), 0.0f);
                float tau = b15d;
                if (dz * dz > tau + eps) dno = false;
                else {
                    float h = sqrtf(fmaxf(tau + eps - dz * dz, 0.0f));
                    int yl, yr; ybounds(h, yl, yr);
                    int rb = dn * NBY;
                    scan(__ldg(&bs[rb + yl]), __ldg(&bs[rb + yr + 1]));
                    dn--;
                }
            }
        }
    }

    if (lane < KNN_K) {
        long long o = ((long long)n * P1 + i) * KNN_K;
        out[o + lane] = (float)lj;
        out[NPK + o + lane] = ld;
    }
}

extern "C" void kernel_launch(void* const* d_in, const int* in_sizes, int n_in,
                              void* d_out, int out_size) {
    const float* pts[2] = {0, 0};
    const int* lens[2] = {0, 0};
    int lsz[2] = {0, 0};
    int psz[2] = {0, 0};
    int npts = 0, nlen = 0;
    for (int i = 0; i < n_in; i++) {
        if (in_sizes[i] <= 1024) {
            if (nlen < 2) { lens[nlen] = (const int*)d_in[i]; lsz[nlen] = in_sizes[i]; nlen++; }
        } else {
            if (npts < 2) { pts[npts] = (const float*)d_in[i]; psz[npts] = in_sizes[i]; npts++; }
        }
    }
    const float* p1 = pts[0];
    const float* p2 = pts[1];
    const int* l1 = lens[0];
    const int* l2 = lens[1];

    int Nn = lsz[0];
    int P1 = psz[0] / (3 * Nn);
    int P2 = psz[1] / (3 * Nn);
    long long NPK = (long long)out_size / 2;   // first half idx, second half dists

    int P = (P1 > P2) ? P1 : P2;
    int ptblocks = (Nn * P + 255) / 256;

    zero_hist_kernel<<<(Nn * NBB + 255) / 256, 256>>>(Nn);
    hist_kernel<<<ptblocks, 256>>>(p1, p2, l1, l2, Nn, P1, P2);
    scan_kernel<<<Nn, 256>>>(Nn);
    scatter_kernel<<<ptblocks, 256>>>(p1, p2, l1, l2, Nn, P1, P2);

    long long threads = (long long)Nn * P1 * 32;
    int blocks = (int)((threads + 255) / 256);
    knn_kernel<<<blocks, 256>>>(p1, l1, (float*)d_out, Nn, P1, P2, NPK);
}

// round 14
// speedup vs baseline: 18.4676x; 1.0031x over previous
#include <cuda_runtime.h>

#define KNN_K 16
#define NBZ   64
#define NBY   64
#define NBB   (NBZ * NBY)
#define C0    64       // bootstrap candidate-count target
#define MAXN  8
#define MAXP  8192
#define FULLM 0xffffffffu
#define FINF  __int_as_float(0x7f800000)

// Fixed bin bounds: correctness holds for ANY bounds (clamped partition);
// these only tune bin quality for ~N(0,1) data.
#define BMIN  (-6.0f)
#define BRNG  (12.0f)
#define WZ    (BRNG / NBZ)
#define INVZ  (NBZ / BRNG)
#define INVY  (NBY / BRNG)

// Static scratch (allocations are forbidden).
__device__ float4 g_pack[MAXN * MAXP];      // bin-sorted targets (x,y,z,idx-bits)
__device__ float  g_s2[MAXN * MAXP];        // bin-sorted ||p2||^2 (reference rounding)
__device__ int    g_qidx[MAXN * MAXP];      // bin-sorted query original index
__device__ int    g_bstart[MAXN * (NBB + 1)];
__device__ int    g_cnt[MAXN * NBB];        // hist counts -> scatter cursors
__device__ int    g_qcnt[MAXN * NBB];

// ||p||^2 with reference rounding: rn(rn(x*x + y*y) + z*z), products rounded.
__device__ __forceinline__ float sumsq_ref(float x, float y, float z) {
    return __fadd_rn(__fadd_rn(__fmul_rn(x, x), __fmul_rn(y, y)),
                     __fmul_rn(z, z));
}

__device__ __forceinline__ int binz(float z) {
    int b = (int)((z - BMIN) * INVZ);
    return min(NBZ - 1, max(0, b));
}
__device__ __forceinline__ int biny(float y) {
    int b = (int)((y - BMIN) * INVY);
    return min(NBY - 1, max(0, b));
}

__global__ void zero_hist_kernel(int Nn) {
    int t = blockIdx.x * blockDim.x + threadIdx.x;
    if (t < Nn * NBB) { g_cnt[t] = 0; g_qcnt[t] = 0; }
}

__global__ void hist_kernel(const float* __restrict__ p1,
                            const float* __restrict__ p2,
                            const int* __restrict__ len1,
                            const int* __restrict__ len2,
                            int Nn, int P1, int P2) {
    int t = blockIdx.x * blockDim.x + threadIdx.x;
    int P = max(P1, P2);
    if (t >= Nn * P) return;
    int n = t / P;
    int j = t - n * P;
    if (j < P2 && j < __ldg(&len2[n])) {
        const float* p = p2 + ((size_t)n * P2 + j) * 3;
        atomicAdd(&g_cnt[n * NBB + binz(p[2]) * NBY + biny(p[1])], 1);
    }
    if (j < P1 && j < __ldg(&len1[n])) {
        const float* p = p1 + ((size_t)n * P1 + j) * 3;
        atomicAdd(&g_qcnt[n * NBB + binz(p[2]) * NBY + biny(p[1])], 1);
    }
}

// One block per batch: two-level exclusive scan of both histograms.
__global__ void scan_kernel(int Nn) {
    int n = blockIdx.x, tid = threadIdx.x;   // 256 threads
    __shared__ int part[256];
    const int BPT = NBB / 256;               // 16 bins per thread

    {
        int base = tid * BPT;
        int cnts[BPT];
        int s = 0;
#pragma unroll
        for (int k = 0; k < BPT; k++) { cnts[k] = g_cnt[n * NBB + base + k]; s += cnts[k]; }
        part[tid] = s; __syncthreads();
        if (tid == 0) {
            int run = 0;
            for (int t = 0; t < 256; t++) { int v = part[t]; part[t] = run; run += v; }
        }
        __syncthreads();
        int run = part[tid];
#pragma unroll
        for (int k = 0; k < BPT; k++) {
            int b = base + k;
            g_bstart[n * (NBB + 1) + b] = run;
            g_cnt[n * NBB + b] = run;
            run += cnts[k];
        }
        if (tid == 255) g_bstart[n * (NBB + 1) + NBB] = run;
        __syncthreads();
    }
    {
        int base = tid * BPT;
        int cnts[BPT];
        int s = 0;
#pragma unroll
        for (int k = 0; k < BPT; k++) { cnts[k] = g_qcnt[n * NBB + base + k]; s += cnts[k]; }
        part[tid] = s; __syncthreads();
        if (tid == 0) {
            int run = 0;
            for (int t = 0; t < 256; t++) { int v = part[t]; part[t] = run; run += v; }
        }
        __syncthreads();
        int run = part[tid];
#pragma unroll
        for (int k = 0; k < BPT; k++) {
            g_qcnt[n * NBB + base + k] = run;
            run += cnts[k];
        }
    }
}

__global__ void scatter_kernel(const float* __restrict__ p1,
                               const float* __restrict__ p2,
                               const int* __restrict__ len1,
                               const int* __restrict__ len2,
                               int Nn, int P1, int P2) {
    int t = blockIdx.x * blockDim.x + threadIdx.x;
    int P = max(P1, P2);
    if (t >= Nn * P) return;
    int n = t / P;
    int j = t - n * P;
    if (j < P2 && j < __ldg(&len2[n])) {
        const float* p = p2 + ((size_t)n * P2 + j) * 3;
        float x = p[0], y = p[1], z = p[2];
        int b = binz(z) * NBY + biny(y);
        int pos = atomicAdd(&g_cnt[n * NBB + b], 1);
        g_pack[n * MAXP + pos] = make_float4(x, y, z, __int_as_float(j));
        g_s2[n * MAXP + pos] = sumsq_ref(x, y, z);
    }
    if (j < P1 && j < __ldg(&len1[n])) {
        const float* p = p1 + ((size_t)n * P1 + j) * 3;
        int b = binz(p[2]) * NBY + biny(p[1]);
        int pos = atomicAdd(&g_qcnt[n * NBB + b], 1);
        g_qidx[n * MAXP + pos] = j;
    }
}

#define LEX_LT(da, ia, db, ib) (((da) < (db)) || (((da) == (db)) && ((ia) < (ib))))

// Warp bitonic sort-32 (ascending lex) of (d, jj) across lanes.
#define BSORT32(d, jj)                                                         \
    _Pragma("unroll")                                                          \
    for (int k = 2; k <= 32; k <<= 1) {                                        \
        _Pragma("unroll")                                                      \
        for (int j = k >> 1; j > 0; j >>= 1) {                                 \
            float od = __shfl_xor_sync(FULLM, d, j);                           \
            int   oj = __shfl_xor_sync(FULLM, jj, j);                          \
            bool up = ((lane & k) == 0);                                       \
            bool want_min = (((lane & j) == 0) == up);                         \
            bool mine_lt = LEX_LT(d, jj, od, oj);                              \
            bool take = (mine_lt != want_min);                                 \
            d = take ? od : d;                                                 \
            jj = take ? oj : jj;                                               \
        }                                                                      \
    }

// One warp per query; warp-distributed sorted top list (lane k = k-th best,
// lex on (d, idx); lanes 16..31 sorted overflow).
__global__ __launch_bounds__(256) void knn_kernel(
    const float* __restrict__ p1,
    const int* __restrict__ len1,
    float* __restrict__ out,
    int Nn, int P1, int P2, long long NPK) {

    int gw = (blockIdx.x * blockDim.x + threadIdx.x) >> 5;
    int lane = threadIdx.x & 31;
    if (gw >= Nn * P1) return;
    int n = gw / P1;
    int qs = gw - n * P1;
    int L1 = __ldg(&len1[n]);
    if (qs >= L1) {
        // Padded slots [L1,P1) biject onto padded rows i=qs: write zeros here.
        if (lane < KNN_K) {
            long long o = ((long long)n * P1 + qs) * KNN_K;
            out[o + lane] = 0.0f;
            out[NPK + o + lane] = 0.0f;
        }
        return;
    }

    int i = __ldg(&g_qidx[n * MAXP + qs]);
    const float* p = p1 + ((size_t)n * P1 + i) * 3;
    float x1 = __ldg(&p[0]), y1 = __ldg(&p[1]), z1 = __ldg(&p[2]);
    float s1 = sumsq_ref(x1, y1, z1);

    const float4* pk = g_pack + (size_t)n * MAXP;
    const float* ps2 = g_s2 + (size_t)n * MAXP;
    const int* bs = g_bstart + n * (NBB + 1);

    int bz = binz(z1);
    int by = biny(y1);

    float ld = FINF; int lj = 0x7fffffff;
    float b15d = FINF; int b15j = 0x7fffffff;
    bool inited = false;
    const float eps = 1e-4f;

    auto scan = [&](int from, int to) {
        int base = from;
        if (!inited && from < to) {
            int t = from + lane;
            float d; int jj;
            if (t < to) {
                float4 q = __ldg(&pk[t]);
                float s2 = __ldg(&ps2[t]);
                float dot = __fmaf_rn(z1, q.z,
                            __fmaf_rn(y1, q.y,
                            __fmul_rn(x1, q.x)));
                d = __fmaf_rn(-2.0f, dot, __fadd_rn(s1, s2));
                jj = __float_as_int(q.w);
            } else { d = FINF; jj = 0x7fffffff; }
            BSORT32(d, jj)
            ld = d; lj = jj;
            b15d = __shfl_sync(FULLM, ld, 15);
            b15j = __shfl_sync(FULLM, lj, 15);
            inited = true;
            base = from + 32;
        }
        for (; base < to; base += 32) {
            int t = base + lane;
            float d; int jj;
            if (t < to) {
                float4 q = __ldg(&pk[t]);
                float s2 = __ldg(&ps2[t]);
                float dot = __fmaf_rn(z1, q.z,
                            __fmaf_rn(y1, q.y,
                            __fmul_rn(x1, q.x)));
                d = __fmaf_rn(-2.0f, dot, __fadd_rn(s1, s2));
                jj = __float_as_int(q.w);
            } else { d = FINF; jj = 0x7fffffff; }
            bool acc = LEX_LT(d, jj, b15d, b15j);
            unsigned am = __ballot_sync(FULLM, acc);
            if (!am) continue;
            if (__popc(am) >= 8) {
                // Bulk path: sort batch, bitonic-merge with list (keep lowest 32).
                BSORT32(d, jj)
                float rd = __shfl_sync(FULLM, d, 31 - lane);
                int   rj = __shfl_sync(FULLM, jj, 31 - lane);
                bool keep = LEX_LT(ld, lj, rd, rj);
                float md = keep ? ld : rd;
                int   mj = keep ? lj : rj;
#pragma unroll
                for (int j = 16; j > 0; j >>= 1) {
                    float od = __shfl_xor_sync(FULLM, md, j);
                    int   oj = __shfl_xor_sync(FULLM, mj, j);
                    bool lower = ((lane & j) == 0);
                    bool mine_lt = LEX_LT(md, mj, od, oj);
                    bool take = (mine_lt != lower);
                    md = take ? od : md;
                    mj = take ? oj : mj;
                }
                ld = md; lj = mj;
            } else {
                while (am) {
                    int src = __ffs(am) - 1;
                    am &= am - 1;
                    float cd = __shfl_sync(FULLM, d, src);
                    int   cj = __shfl_sync(FULLM, jj, src);
                    float pd = __shfl_up_sync(FULLM, ld, 1);
                    int   pj = __shfl_up_sync(FULLM, lj, 1);
                    if (LEX_LT(cd, cj, ld, lj)) {
                        bool here = (lane == 0) || LEX_LT(pd, pj, cd, cj);
                        ld = here ? cd : pd;
                        lj = here ? cj : pj;
                    }
                }
            }
            b15d = __shfl_sync(FULLM, ld, 15);
            b15j = __shfl_sync(FULLM, lj, 15);
        }
    };

    // y-window [yl, yr] for half-width h around y1 (float-clamped: h may be inf).
    auto ybounds = [&](float h, int& yl, int& yr) {
        float fl = (y1 - h - BMIN) * INVY;
        float fr = (y1 + h - BMIN) * INVY;
        yl = (int)fminf(fmaxf(fl, 0.0f), (float)(NBY - 1));
        yr = (int)fminf(fmaxf(fr, 0.0f), (float)(NBY - 1));
    };

    // Bootstrap: register-preloaded boundaries bs[rowb+by-15 .. by+16] (one
    // coalesced lane load); the count expansion runs on shfl, no memory.
    int rowb = bz * NBY;
    int pbase = by - 15;                       // boundary idx offset within row
    {
        int bidx = min(max(pbase + lane, 0), NBY);
        int pv = __ldg(&bs[rowb + bidx]);
        auto bget = [&](int yb) -> int {       // boundary at row offset yb (0..NBY)
            if (yb >= pbase && yb < pbase + 32)
                return __shfl_sync(FULLM, pv, yb - pbase);
            return __ldg(&bs[rowb + yb]);
        };

        int ylo0 = by, yhi0 = by;
        int from = bget(ylo0), to = bget(yhi0 + 1);
        bool side = true;
        while (to - from < C0) {
            bool canR = (yhi0 < NBY - 1), canL = (ylo0 > 0);
            if (!canR && !canL) break;
            if ((side && canR) || !canL) { yhi0++; to = bget(yhi0 + 1); }
            else { ylo0--; from = bget(ylo0); }
            side = !side;
        }
        scan(from, to);

        // Own-row remainder (disjoint; stale tau => superset, exact).
        float tau = b15d;
        float h = sqrtf(fmaxf(tau + eps, 0.0f));
        int yl, yr; ybounds(h, yl, yr);
        if (yl < ylo0) scan(bget(yl), bget(ylo0));
        if (yr > yhi0) scan(bget(yhi0 + 1), bget(yr + 1));
    }

    // Rows outward with exact per-direction stop.
    int up = bz + 1, dn = bz - 1;
    bool uo = true, dno = true;
    while (uo || dno) {
        if (uo) {
            if (up >= NBZ) uo = false;
            else {
                float dz = fmaxf(BMIN + (float)up * WZ - z1, 0.0f);
                float tau = b15d;
                if (dz * dz > tau + eps) uo = false;
                else {
                    float h = sqrtf(fmaxf(tau + eps - dz * dz, 0.0f));
                    int yl, yr; ybounds(h, yl, yr);
                    int rb = up * NBY;
                    scan(__ldg(&bs[rb + yl]), __ldg(&bs[rb + yr + 1]));
                    up++;
                }
            }
        }
        if (dno) {
            if (dn < 0) dno = false;
            else {
                float dz = fmaxf(z1 - (BMIN + (float)(dn + 1) * WZ), 0.0f);
                float tau = b15d;
                if (dz * dz > tau + eps) dno = false;
                else {
                    float h = sqrtf(fmaxf(tau + eps - dz * dz, 0.0f));
                    int yl, yr; ybounds(h, yl, yr);
                    int rb = dn * NBY;
                    scan(__ldg(&bs[rb + yl]), __ldg(&bs[rb + yr + 1]));
                    dn--;
                }
            }
        }
    }

    if (lane < KNN_K) {
        long long o = ((long long)n * P1 + i) * KNN_K;
        out[o + lane] = (float)lj;
        out[NPK + o + lane] = ld;
    }
}

extern "C" void kernel_launch(void* const* d_in, const int* in_sizes, int n_in,
                              void* d_out, int out_size) {
    const float* pts[2] = {0, 0};
    const int* lens[2] = {0, 0};
    int lsz[2] = {0, 0};
    int psz[2] = {0, 0};
    int npts = 0, nlen = 0;
    for (int i = 0; i < n_in; i++) {
        if (in_sizes[i] <= 1024) {
            if (nlen < 2) { lens[nlen] = (const int*)d_in[i]; lsz[nlen] = in_sizes[i]; nlen++; }
        } else {
            if (npts < 2) { pts[npts] = (const float*)d_in[i]; psz[npts] = in_sizes[i]; npts++; }
        }
    }
    const float* p1 = pts[0];
    const float* p2 = pts[1];
    const int* l1 = lens[0];
    const int* l2 = lens[1];

    int Nn = lsz[0];
    int P1 = psz[0] / (3 * Nn);
    int P2 = psz[1] / (3 * Nn);
    long long NPK = (long long)out_size / 2;   // first half idx, second half dists

    int P = (P1 > P2) ? P1 : P2;
    int ptblocks = (Nn * P + 255) / 256;

    zero_hist_kernel<<<(Nn * NBB + 255) / 256, 256>>>(Nn);
    hist_kernel<<<ptblocks, 256>>>(p1, p2, l1, l2, Nn, P1, P2);
    scan_kernel<<<Nn, 256>>>(Nn);
    scatter_kernel<<<ptblocks, 256>>>(p1, p2, l1, l2, Nn, P1, P2);

    long long threads = (long long)Nn * P1 * 32;
    int blocks = (int)((threads + 255) / 256);
    knn_kernel<<<blocks, 256>>>(p1, l1, (float*)d_out, Nn, P1, P2, NPK);
}